// round 3
// baseline (speedup 1.0000x reference)
#include <cuda_runtime.h>
#include <cstddef>

// Problem constants (static per reference)
#define NB  8
#define LQn 2048
#define CC  256
#define MH  8
#define LLv 4
#define PPt 4
#define DHd 32
#define SSt 3840
#define MLP 128   // M*L*P

// Scratch (allocation-free rule: __device__ globals)
__device__ float g_value[(size_t)NB * SSt * CC];   // (N,S,M,DH)
__device__ float g_off  [(size_t)NB * LQn * MLP];
__device__ float g_attn [(size_t)NB * LQn * MLP];
__device__ float g_tmp  [(size_t)NB * LQn * CC];   // deform output (N,LQ,M,DH)
__device__ float g_loc2 [(size_t)NB * LQn * MLP];  // fallback loc/attn storage
__device__ float g_att2 [(size_t)NB * LQn * MLP];

// ---------------------------------------------------------------------------
// SGEMM: C[Mr,Nc] = A[Mr,K] * B[K,Nc] + bias[Nc]   (all row-major)
// BM=128, BN=64, BK=16, 256 threads, TM=8, TN=4
// ---------------------------------------------------------------------------
__global__ __launch_bounds__(256) void sgemm_bias_kernel(
    const float* __restrict__ A, const float* __restrict__ B,
    const float* __restrict__ bias, float* __restrict__ Cmat,
    int Mr, int Nc, int K)
{
    const int BM = 128, BN = 64, BK = 16;
    __shared__ float As[BK][BM];
    __shared__ float Bs[BK][BN];

    int tid = threadIdx.x;         // 0..255
    int tx  = tid & 15;            // 16 col groups * TN=4 -> 64
    int ty  = tid >> 4;            // 16 row groups * TM=8 -> 128
    int bm  = blockIdx.y * BM;
    int bn  = blockIdx.x * BN;

    float acc[8][4];
    #pragma unroll
    for (int i = 0; i < 8; i++)
        #pragma unroll
        for (int j = 0; j < 4; j++) acc[i][j] = 0.f;

    int a_row = tid >> 2;          // 0..63 (handles rows a_row, a_row+64)
    int a_col = (tid & 3) * 4;
    int b_row = tid >> 4;          // 0..15
    int b_col = (tid & 15) * 4;

    for (int k0 = 0; k0 < K; k0 += BK) {
        #pragma unroll
        for (int r = 0; r < 2; r++) {
            int row = a_row + r * 64;
            float4 v = *(const float4*)(A + (size_t)(bm + row) * K + k0 + a_col);
            As[a_col + 0][row] = v.x;
            As[a_col + 1][row] = v.y;
            As[a_col + 2][row] = v.z;
            As[a_col + 3][row] = v.w;
        }
        float4 vb = *(const float4*)(B + (size_t)(k0 + b_row) * Nc + bn + b_col);
        *(float4*)&Bs[b_row][b_col] = vb;
        __syncthreads();

        #pragma unroll
        for (int k = 0; k < BK; k++) {
            float ra[8], rb[4];
            #pragma unroll
            for (int i = 0; i < 8; i++) ra[i] = As[k][ty * 8 + i];
            #pragma unroll
            for (int j = 0; j < 4; j++) rb[j] = Bs[k][tx * 4 + j];
            #pragma unroll
            for (int i = 0; i < 8; i++)
                #pragma unroll
                for (int j = 0; j < 4; j++)
                    acc[i][j] += ra[i] * rb[j];
        }
        __syncthreads();
    }

    #pragma unroll
    for (int i = 0; i < 8; i++) {
        int row = bm + ty * 8 + i;
        #pragma unroll
        for (int j = 0; j < 4; j++) {
            int col = bn + tx * 4 + j;
            Cmat[(size_t)row * Nc + col] = acc[i][j] + bias[col];
        }
    }
}

// ---------------------------------------------------------------------------
// Postprocess: loc = ref + off/norm ; attn = softmax(logits over 16)
// One thread per (n,q,m). Writes loc/attn (these are outputs #2, #3).
// ---------------------------------------------------------------------------
__global__ __launch_bounds__(256) void postproc_kernel(
    const float* __restrict__ refpts,
    float* __restrict__ loc_out, float* __restrict__ attn_out)
{
    int idx = blockIdx.x * blockDim.x + threadIdx.x;   // nqm
    if (idx >= NB * LQn * MH) return;
    int m  = idx % MH;
    int nq = idx / MH;

    const float norm[4] = {2048.f, 1024.f, 512.f, 256.f};
    const float* off = g_off  + (size_t)nq * MLP + m * 16;
    const float* lg  = g_attn + (size_t)nq * MLP + m * 16;

    float logits[16], lmax = -1e30f;
    #pragma unroll
    for (int i = 0; i < 16; i++) { logits[i] = lg[i]; lmax = fmaxf(lmax, logits[i]); }
    float sum = 0.f;
    #pragma unroll
    for (int i = 0; i < 16; i++) { logits[i] = __expf(logits[i] - lmax); sum += logits[i]; }
    float inv = 1.f / sum;

    size_t base = (size_t)idx * 16;
    #pragma unroll
    for (int l = 0; l < 4; l++) {
        float rp = refpts[(size_t)nq * LLv + l];
        #pragma unroll
        for (int p = 0; p < 4; p++) {
            int i = l * 4 + p;
            loc_out [base + i] = rp + off[i] / norm[l];
            attn_out[base + i] = logits[i] * inv;
        }
    }
}

// ---------------------------------------------------------------------------
// Deformable sampling: warp per (n,q,m), lane = channel d (DH=32).
// 16 bilinear samples from g_value (L2-resident), weighted by attn.
// ---------------------------------------------------------------------------
__global__ __launch_bounds__(256) void sample_kernel(
    const float* __restrict__ loc, const float* __restrict__ attnw)
{
    int gwarp = (blockIdx.x * blockDim.x + threadIdx.x) >> 5;
    int lane  = threadIdx.x & 31;
    if (gwarp >= NB * LQn * MH) return;
    int m  = gwarp % MH;
    int nq = gwarp / MH;
    int n  = nq / LQn;

    const int lens[4]   = {2048, 1024, 512, 256};
    const int starts[4] = {0, 2048, 3072, 3584};

    size_t base16 = (size_t)gwarp * 16;
    float acc = 0.f;

    #pragma unroll
    for (int l = 0; l < 4; l++) {
        int T  = lens[l];
        int st = starts[l];
        const float* vbase = g_value + ((((size_t)n * SSt + st) * MH + m) * DHd) + lane;
        #pragma unroll
        for (int p = 0; p < 4; p++) {
            int i = l * 4 + p;
            float a   = attnw[base16 + i];
            float pos = loc[base16 + i] * (float)T - 0.5f;
            float x0f = floorf(pos);
            float frac = pos - x0f;
            int x0 = (int)x0f;
            float w0 = (x0 >= 0 && x0 < T)         ? (1.f - frac) : 0.f;
            float w1 = (x0 + 1 >= 0 && x0 + 1 < T) ? frac         : 0.f;
            int i0 = min(max(x0, 0), T - 1);
            int i1 = min(max(x0 + 1, 0), T - 1);
            float v0 = vbase[(size_t)i0 * (MH * DHd)];
            float v1 = vbase[(size_t)i1 * (MH * DHd)];
            acc += a * (w0 * v0 + w1 * v1);
        }
    }
    g_tmp[(size_t)gwarp * DHd + lane] = acc;
}

// ---------------------------------------------------------------------------
extern "C" void kernel_launch(void* const* d_in, const int* in_sizes, int n_in,
                              void* d_out, int out_size)
{
    const float* query  = (const float*)d_in[0];
    const float* refpts = (const float*)d_in[1];
    const float* inp    = (const float*)d_in[2];
    // d_in[3], d_in[4]: temporal_lens / level_start_index (static, baked)
    const float* W_off  = (const float*)d_in[5];
    const float* b_off  = (const float*)d_in[6];
    const float* W_attn = (const float*)d_in[7];
    const float* b_attn = (const float*)d_in[8];
    const float* W_val  = (const float*)d_in[9];
    const float* b_val  = (const float*)d_in[10];
    const float* W_out  = (const float*)d_in[11];
    const float* b_out  = (const float*)d_in[12];
    float* out = (float*)d_out;

    // Resolve scratch symbol addresses (pure host queries — graph-safe)
    float *p_value, *p_off, *p_attn, *p_tmp, *p_loc2, *p_att2;
    cudaGetSymbolAddress((void**)&p_value, g_value);
    cudaGetSymbolAddress((void**)&p_off,   g_off);
    cudaGetSymbolAddress((void**)&p_attn,  g_attn);
    cudaGetSymbolAddress((void**)&p_tmp,   g_tmp);
    cudaGetSymbolAddress((void**)&p_loc2,  g_loc2);
    cudaGetSymbolAddress((void**)&p_att2,  g_att2);

    const int out_elems  = NB * LQn * CC;        // 4194304
    const int locattn    = NB * LQn * MLP;       // 1048576
    bool full_out = (out_size >= out_elems + 2 * locattn);
    float* loc_out  = full_out ? (out + out_elems)           : p_loc2;
    float* attn_out = full_out ? (out + out_elems + locattn) : p_att2;

    // 1) value = input_flatten @ W_val + b_val   (30720 x 256 x 256)
    {
        dim3 grid(CC / 64, (NB * SSt) / 128);
        sgemm_bias_kernel<<<grid, 256>>>(inp, W_val, b_val, p_value, NB * SSt, CC, CC);
    }
    // 2) off logits  (16384 x 128 x 256)
    {
        dim3 grid(MLP / 64, (NB * LQn) / 128);
        sgemm_bias_kernel<<<grid, 256>>>(query, W_off, b_off, p_off, NB * LQn, MLP, CC);
    }
    // 3) attn logits (16384 x 128 x 256)
    {
        dim3 grid(MLP / 64, (NB * LQn) / 128);
        sgemm_bias_kernel<<<grid, 256>>>(query, W_attn, b_attn, p_attn, NB * LQn, MLP, CC);
    }
    // 4) loc + softmax -> outputs 2 & 3
    {
        int total = NB * LQn * MH;
        postproc_kernel<<<(total + 255) / 256, 256>>>(refpts, loc_out, attn_out);
    }
    // 5) deformable sampling -> g_tmp (N,LQ,C)
    {
        int totalThreads = NB * LQn * MH * 32;
        sample_kernel<<<totalThreads / 256, 256>>>(loc_out, attn_out);
    }
    // 6) out = g_tmp @ W_out + b_out  (16384 x 256 x 256) -> output 1
    {
        dim3 grid(CC / 64, (NB * LQn) / 128);
        sgemm_bias_kernel<<<grid, 256>>>(p_tmp, W_out, b_out, out, NB * LQn, CC, CC);
    }
}

// round 6
// speedup vs baseline: 1.5694x; 1.5694x over previous
#include <cuda_runtime.h>
#include <cuda_bf16.h>
#include <cstdint>
#include <cstddef>

// Problem constants (static per reference)
#define NB  8
#define LQn 2048
#define CC  256
#define MH  8
#define LLv 4
#define DHd 32
#define SSt 3840
#define MLP 128   // M*L*P
#define KK  256   // GEMM K (= C)

#define ASTR 40        // smem row stride in bf16 elems (80 B; 16B-aligned, conflict-free)
#define TILE_B (128 * ASTR * 2)   // 10240 B per 128x32 bf16 tile

// ---------------- scratch (__device__ globals; allocation-free rule) -------
__device__ float g_value [(size_t)NB * SSt * CC];   // value (N,S,M,DH) fp32
__device__ float g_logits[(size_t)NB * LQn * 256];  // [off(128) | attn(128)]
__device__ float g_tmp   [(size_t)NB * LQn * CC];   // deform output
__device__ float g_loc2  [(size_t)NB * LQn * MLP];  // fallback outputs
__device__ float g_att2  [(size_t)NB * LQn * MLP];
__device__ float g_bcat  [256];

// bf16 hi/lo split activations (A matrices, row-major [R][256])
__device__ __nv_bfloat16 g_aih[(size_t)NB * SSt * KK];
__device__ __nv_bfloat16 g_ail[(size_t)NB * SSt * KK];
__device__ __nv_bfloat16 g_aqh[(size_t)NB * LQn * KK];
__device__ __nv_bfloat16 g_aql[(size_t)NB * LQn * KK];
__device__ __nv_bfloat16 g_ath[(size_t)NB * LQn * KK];
__device__ __nv_bfloat16 g_atl[(size_t)NB * LQn * KK];
// bf16 hi/lo transposed weights (B matrices, [Nc][256] K-major)
__device__ __nv_bfloat16 g_bvh[256 * KK], g_bvl[256 * KK];  // W_val^T
__device__ __nv_bfloat16 g_bch[256 * KK], g_bcl[256 * KK];  // [W_off|W_attn]^T
__device__ __nv_bfloat16 g_boh[256 * KK], g_bol[256 * KK];  // W_out^T

__device__ __forceinline__ uint32_t smem_u32(const void* p) {
    uint32_t a;
    asm("{ .reg .u64 t; cvta.to.shared.u64 t, %1; cvt.u32.u64 %0, t; }"
        : "=r"(a) : "l"(p));
    return a;
}

// ---------------------------------------------------------------------------
// mma.sync GEMM: C[Mr,Nc] = (Ah+Al)[Mr,256] x (Bh+Bl)[Nc,256]^T + bias
// 3-term bf16 split, fp32 accumulate. CTA tile 128x128, 8 warps (64x32 each),
// BK=32, 2-stage cp.async pipeline.
// ---------------------------------------------------------------------------
__global__ __launch_bounds__(256, 1)
void gemm_mma_kernel(const __nv_bfloat16* __restrict__ Ah,
                     const __nv_bfloat16* __restrict__ Al,
                     const __nv_bfloat16* __restrict__ Bh,
                     const __nv_bfloat16* __restrict__ Bl,
                     const float* __restrict__ bias,
                     float* __restrict__ Cmat, int Nc)
{
    extern __shared__ __align__(128) char smem[];
    uint32_t sb = smem_u32(smem);
    int tid  = threadIdx.x;
    int lane = tid & 31;
    int wid  = tid >> 5;
    int wr   = wid >> 2;     // 0..1  (m warp row)
    int wc   = wid & 3;      // 0..3  (n warp col)
    int bm   = blockIdx.y * 128;
    int bn   = blockIdx.x * 128;

    const __nv_bfloat16* gtab[4] = {Ah + (size_t)bm * KK, Al + (size_t)bm * KK,
                                    Bh + (size_t)bn * KK, Bl + (size_t)bn * KK};
    int srow  = tid >> 1;          // 0..127
    int sboff = (tid & 1) * 32;    // 0 or 32 bytes within 64B row chunk

    float acc[4][4][4];
    #pragma unroll
    for (int i = 0; i < 4; i++)
        #pragma unroll
        for (int j = 0; j < 4; j++)
            #pragma unroll
            for (int r = 0; r < 4; r++) acc[i][j][r] = 0.f;

    // lane-derived ldmatrix offsets
    int a_r = lane & 15;                 // row within 16
    int a_k = (lane >> 4) << 3;          // 0 / 8 (k-halves)
    int b_r = lane & 7;
    int b_k = ((lane >> 3) & 1) << 3;

    // ---- staging (cp.async, 16B chunks) ----
    #define STAGE_LOAD(s, k0) do {                                              \
        _Pragma("unroll")                                                       \
        for (int t = 0; t < 4; t++) {                                           \
            uint32_t sdst = sb + (uint32_t)((s) * 4 + t) * TILE_B               \
                          + (uint32_t)srow * (ASTR * 2) + sboff;                \
            const char* gsrc = (const char*)(gtab[t] + (size_t)srow * KK + (k0))\
                             + sboff;                                           \
            asm volatile("cp.async.cg.shared.global [%0], [%1], 16;"            \
                         :: "r"(sdst), "l"(gsrc));                              \
            asm volatile("cp.async.cg.shared.global [%0], [%1], 16;"            \
                         :: "r"(sdst + 16), "l"(gsrc + 16));                    \
        }                                                                       \
        asm volatile("cp.async.commit_group;" ::: "memory");                    \
    } while (0)

    STAGE_LOAD(0, 0);

    for (int kt = 0; kt < 8; kt++) {
        if (kt < 7) {
            STAGE_LOAD((kt + 1) & 1, (kt + 1) * 32);
            asm volatile("cp.async.wait_group 1;" ::: "memory");
        } else {
            asm volatile("cp.async.wait_group 0;" ::: "memory");
        }
        __syncthreads();

        int s = kt & 1;
        uint32_t sAh = sb + (uint32_t)(s * 4 + 0) * TILE_B;
        uint32_t sAl = sb + (uint32_t)(s * 4 + 1) * TILE_B;
        uint32_t sBh = sb + (uint32_t)(s * 4 + 2) * TILE_B;
        uint32_t sBl = sb + (uint32_t)(s * 4 + 3) * TILE_B;

        #pragma unroll
        for (int kk = 0; kk < 32; kk += 16) {
            uint32_t ah[4][4], al[4][4], bh[4][2], bl[4][2];
            #pragma unroll
            for (int mi = 0; mi < 4; mi++) {
                int row = wr * 64 + mi * 16 + a_r;
                uint32_t off = (uint32_t)(row * ASTR + kk + a_k) * 2;
                asm volatile(
                    "ldmatrix.sync.aligned.m8n8.x4.shared.b16 {%0,%1,%2,%3}, [%4];"
                    : "=r"(ah[mi][0]), "=r"(ah[mi][1]), "=r"(ah[mi][2]), "=r"(ah[mi][3])
                    : "r"(sAh + off));
                asm volatile(
                    "ldmatrix.sync.aligned.m8n8.x4.shared.b16 {%0,%1,%2,%3}, [%4];"
                    : "=r"(al[mi][0]), "=r"(al[mi][1]), "=r"(al[mi][2]), "=r"(al[mi][3])
                    : "r"(sAl + off));
            }
            #pragma unroll
            for (int ni = 0; ni < 4; ni++) {
                int row = wc * 32 + ni * 8 + b_r;
                uint32_t off = (uint32_t)(row * ASTR + kk + b_k) * 2;
                asm volatile(
                    "ldmatrix.sync.aligned.m8n8.x2.shared.b16 {%0,%1}, [%2];"
                    : "=r"(bh[ni][0]), "=r"(bh[ni][1]) : "r"(sBh + off));
                asm volatile(
                    "ldmatrix.sync.aligned.m8n8.x2.shared.b16 {%0,%1}, [%2];"
                    : "=r"(bl[ni][0]), "=r"(bl[ni][1]) : "r"(sBl + off));
            }

            #define MMA(ACC, A, B)                                              \
                asm volatile(                                                   \
                    "mma.sync.aligned.m16n8k16.row.col.f32.bf16.bf16.f32 "      \
                    "{%0,%1,%2,%3}, {%4,%5,%6,%7}, {%8,%9}, {%0,%1,%2,%3};"     \
                    : "+f"((ACC)[0]), "+f"((ACC)[1]), "+f"((ACC)[2]), "+f"((ACC)[3]) \
                    : "r"((A)[0]), "r"((A)[1]), "r"((A)[2]), "r"((A)[3]),       \
                      "r"((B)[0]), "r"((B)[1]))

            #pragma unroll
            for (int mi = 0; mi < 4; mi++)
                #pragma unroll
                for (int ni = 0; ni < 4; ni++) {
                    MMA(acc[mi][ni], ah[mi], bh[ni]);   // Ah*Bh
                    MMA(acc[mi][ni], al[mi], bh[ni]);   // Al*Bh
                    MMA(acc[mi][ni], ah[mi], bl[ni]);   // Ah*Bl
                }
            #undef MMA
        }
        __syncthreads();
    }
    #undef STAGE_LOAD

    // ---- epilogue: fp32 + bias ----
    int r0 = bm + wr * 64;
    int c0 = bn + wc * 32;
    #pragma unroll
    for (int mi = 0; mi < 4; mi++) {
        int row = r0 + mi * 16 + (lane >> 2);
        #pragma unroll
        for (int ni = 0; ni < 4; ni++) {
            int col = c0 + ni * 8 + (lane & 3) * 2;
            float2 bv = *(const float2*)(bias + col);
            float2 v0 = {acc[mi][ni][0] + bv.x, acc[mi][ni][1] + bv.y};
            float2 v1 = {acc[mi][ni][2] + bv.x, acc[mi][ni][3] + bv.y};
            *(float2*)(Cmat + (size_t)row * Nc + col)       = v0;
            *(float2*)(Cmat + (size_t)(row + 8) * Nc + col) = v1;
        }
    }
}

// ---------------------------------------------------------------------------
// fp32 -> bf16 hi/lo split, vectorized
// ---------------------------------------------------------------------------
__global__ __launch_bounds__(256) void convA_kernel(
    const float* __restrict__ src, __nv_bfloat16* __restrict__ hi,
    __nv_bfloat16* __restrict__ lo, int n4)
{
    int i = blockIdx.x * blockDim.x + threadIdx.x;
    if (i >= n4) return;
    float4 v = ((const float4*)src)[i];
    __nv_bfloat16 h0 = __float2bfloat16(v.x), h1 = __float2bfloat16(v.y);
    __nv_bfloat16 h2 = __float2bfloat16(v.z), h3 = __float2bfloat16(v.w);
    __nv_bfloat16 l0 = __float2bfloat16(v.x - __bfloat162float(h0));
    __nv_bfloat16 l1 = __float2bfloat16(v.y - __bfloat162float(h1));
    __nv_bfloat16 l2 = __float2bfloat16(v.z - __bfloat162float(h2));
    __nv_bfloat16 l3 = __float2bfloat16(v.w - __bfloat162float(h3));
    __nv_bfloat162* H = (__nv_bfloat162*)hi;
    __nv_bfloat162* L = (__nv_bfloat162*)lo;
    H[2 * i]     = __nv_bfloat162(h0, h1);
    H[2 * i + 1] = __nv_bfloat162(h2, h3);
    L[2 * i]     = __nv_bfloat162(l0, l1);
    L[2 * i + 1] = __nv_bfloat162(l2, l3);
}

// W[K,Nc] (optionally two concatenated sources) -> Bt[Nc][256] bf16 hi/lo
__global__ __launch_bounds__(256) void transconv_kernel(
    const float* __restrict__ src0, const float* __restrict__ src1,
    int split, int Nc, __nv_bfloat16* __restrict__ bh, __nv_bfloat16* __restrict__ bl)
{
    int idx = blockIdx.x * blockDim.x + threadIdx.x;
    if (idx >= Nc * KK) return;
    int n = idx >> 8, k = idx & 255;
    float v = (n < split) ? src0[(size_t)k * split + n]
                          : src1[(size_t)k * (Nc - split) + (n - split)];
    __nv_bfloat16 h = __float2bfloat16(v);
    bh[idx] = h;
    bl[idx] = __float2bfloat16(v - __bfloat162float(h));
}

__global__ void biascat_kernel(const float* __restrict__ b0,
                               const float* __restrict__ b1, float* __restrict__ dst)
{
    int i = threadIdx.x;
    dst[i] = (i < 128) ? b0[i] : b1[i - 128];
}

// ---------------------------------------------------------------------------
// Postproc: loc = ref + off/norm ; attn = softmax over 16. Vectorized float4.
// ---------------------------------------------------------------------------
__global__ __launch_bounds__(256) void postproc_kernel(
    const float* __restrict__ refpts, const float* __restrict__ logits,
    float* __restrict__ loc_out, float* __restrict__ attn_out)
{
    int idx = blockIdx.x * blockDim.x + threadIdx.x;   // (n,q,m)
    if (idx >= NB * LQn * MH) return;
    int m  = idx & 7;
    int nq = idx >> 3;

    const float4* off4 = (const float4*)(logits + (size_t)nq * 256 + m * 16);
    const float4* lg4  = (const float4*)(logits + (size_t)nq * 256 + 128 + m * 16);
    float4 L0 = lg4[0], L1 = lg4[1], L2 = lg4[2], L3 = lg4[3];
    float lg[16] = {L0.x, L0.y, L0.z, L0.w, L1.x, L1.y, L1.z, L1.w,
                    L2.x, L2.y, L2.z, L2.w, L3.x, L3.y, L3.z, L3.w};
    float mx = lg[0];
    #pragma unroll
    for (int i = 1; i < 16; i++) mx = fmaxf(mx, lg[i]);
    float sum = 0.f;
    #pragma unroll
    for (int i = 0; i < 16; i++) { lg[i] = __expf(lg[i] - mx); sum += lg[i]; }
    float inv = 1.f / sum;

    float4 refv = ((const float4*)refpts)[nq];         // (N,LQ,L,1): 4 per nq
    const float rn[4] = {refv.x, refv.y, refv.z, refv.w};
    const float innorm[4] = {1.f / 2048.f, 1.f / 1024.f, 1.f / 512.f, 1.f / 256.f};

    float4* lo4 = (float4*)(loc_out  + (size_t)idx * 16);
    float4* at4 = (float4*)(attn_out + (size_t)idx * 16);
    #pragma unroll
    for (int l = 0; l < 4; l++) {
        float4 o = off4[l];
        float4 lv;
        lv.x = rn[l] + o.x * innorm[l];
        lv.y = rn[l] + o.y * innorm[l];
        lv.z = rn[l] + o.z * innorm[l];
        lv.w = rn[l] + o.w * innorm[l];
        lo4[l] = lv;
        float4 av = {lg[l * 4] * inv, lg[l * 4 + 1] * inv,
                     lg[l * 4 + 2] * inv, lg[l * 4 + 3] * inv};
        at4[l] = av;
    }
}

// ---------------------------------------------------------------------------
// Deformable sampling: warp per (n,q,m), lane = channel d (DH=32)
// ---------------------------------------------------------------------------
__global__ __launch_bounds__(256) void sample_kernel(
    const float* __restrict__ loc, const float* __restrict__ attnw)
{
    int gwarp = (blockIdx.x * blockDim.x + threadIdx.x) >> 5;
    int lane  = threadIdx.x & 31;
    if (gwarp >= NB * LQn * MH) return;
    int m  = gwarp % MH;
    int nq = gwarp / MH;
    int n  = nq / LQn;

    const int lens[4]   = {2048, 1024, 512, 256};
    const int starts[4] = {0, 2048, 3072, 3584};

    size_t base16 = (size_t)gwarp * 16;
    float acc = 0.f;

    #pragma unroll
    for (int l = 0; l < 4; l++) {
        int T  = lens[l];
        int st = starts[l];
        const float* vbase = g_value + ((((size_t)n * SSt + st) * MH + m) * DHd) + lane;
        #pragma unroll
        for (int p = 0; p < 4; p++) {
            int i = l * 4 + p;
            float a   = attnw[base16 + i];
            float pos = loc[base16 + i] * (float)T - 0.5f;
            float x0f = floorf(pos);
            float frac = pos - x0f;
            int x0 = (int)x0f;
            float w0 = (x0 >= 0 && x0 < T)         ? (1.f - frac) : 0.f;
            float w1 = (x0 + 1 >= 0 && x0 + 1 < T) ? frac         : 0.f;
            int i0 = min(max(x0, 0), T - 1);
            int i1 = min(max(x0 + 1, 0), T - 1);
            float v0 = vbase[(size_t)i0 * (MH * DHd)];
            float v1 = vbase[(size_t)i1 * (MH * DHd)];
            acc += a * (w0 * v0 + w1 * v1);
        }
    }
    g_tmp[(size_t)gwarp * DHd + lane] = acc;
}

// ---------------------------------------------------------------------------
extern "C" void kernel_launch(void* const* d_in, const int* in_sizes, int n_in,
                              void* d_out, int out_size)
{
    const float* query  = (const float*)d_in[0];
    const float* refpts = (const float*)d_in[1];
    const float* inp    = (const float*)d_in[2];
    const float* W_off  = (const float*)d_in[5];
    const float* b_off  = (const float*)d_in[6];
    const float* W_attn = (const float*)d_in[7];
    const float* b_attn = (const float*)d_in[8];
    const float* W_val  = (const float*)d_in[9];
    const float* b_val  = (const float*)d_in[10];
    const float* W_out  = (const float*)d_in[11];
    const float* b_out  = (const float*)d_in[12];
    float* out = (float*)d_out;

    float *p_value, *p_logits, *p_tmp, *p_loc2, *p_att2, *p_bcat;
    __nv_bfloat16 *p_aih, *p_ail, *p_aqh, *p_aql, *p_ath, *p_atl;
    __nv_bfloat16 *p_bvh, *p_bvl, *p_bch, *p_bcl, *p_boh, *p_bol;
    cudaGetSymbolAddress((void**)&p_value,  g_value);
    cudaGetSymbolAddress((void**)&p_logits, g_logits);
    cudaGetSymbolAddress((void**)&p_tmp,    g_tmp);
    cudaGetSymbolAddress((void**)&p_loc2,   g_loc2);
    cudaGetSymbolAddress((void**)&p_att2,   g_att2);
    cudaGetSymbolAddress((void**)&p_bcat,   g_bcat);
    cudaGetSymbolAddress((void**)&p_aih, g_aih);  cudaGetSymbolAddress((void**)&p_ail, g_ail);
    cudaGetSymbolAddress((void**)&p_aqh, g_aqh);  cudaGetSymbolAddress((void**)&p_aql, g_aql);
    cudaGetSymbolAddress((void**)&p_ath, g_ath);  cudaGetSymbolAddress((void**)&p_atl, g_atl);
    cudaGetSymbolAddress((void**)&p_bvh, g_bvh);  cudaGetSymbolAddress((void**)&p_bvl, g_bvl);
    cudaGetSymbolAddress((void**)&p_bch, g_bch);  cudaGetSymbolAddress((void**)&p_bcl, g_bcl);
    cudaGetSymbolAddress((void**)&p_boh, g_boh);  cudaGetSymbolAddress((void**)&p_bol, g_bol);

    const int out_elems = NB * LQn * CC;        // 4194304
    const int locattn   = NB * LQn * MLP;       // 1048576
    bool full_out = (out_size >= out_elems + 2 * locattn);
    float* loc_out  = full_out ? (out + out_elems)           : p_loc2;
    float* attn_out = full_out ? (out + out_elems + locattn) : p_att2;

    const int smem_bytes = 8 * TILE_B;          // 81920
    cudaFuncSetAttribute(gemm_mma_kernel,
                         cudaFuncAttributeMaxDynamicSharedMemorySize, smem_bytes);

    // ---- weight prep (tiny) ----
    transconv_kernel<<<(256 * KK) / 256, 256>>>(W_val,  W_val,  256, 256, p_bvh, p_bvl);
    transconv_kernel<<<(256 * KK) / 256, 256>>>(W_off,  W_attn, 128, 256, p_bch, p_bcl);
    transconv_kernel<<<(256 * KK) / 256, 256>>>(W_out,  W_out,  256, 256, p_boh, p_bol);
    biascat_kernel<<<1, 256>>>(b_off, b_attn, p_bcat);

    // ---- activation conversions ----
    {
        int n4 = NB * SSt * KK / 4;
        convA_kernel<<<(n4 + 255) / 256, 256>>>(inp, p_aih, p_ail, n4);
    }
    {
        int n4 = NB * LQn * KK / 4;
        convA_kernel<<<(n4 + 255) / 256, 256>>>(query, p_aqh, p_aql, n4);
    }

    // ---- value = inp @ W_val + b_val  (30720 x 256) ----
    {
        dim3 grid(256 / 128, (NB * SSt) / 128);
        gemm_mma_kernel<<<grid, 256, smem_bytes>>>(p_aih, p_ail, p_bvh, p_bvl,
                                                   b_val, p_value, 256);
    }
    // ---- logits = query @ [W_off|W_attn] + bcat  (16384 x 256) ----
    {
        dim3 grid(256 / 128, (NB * LQn) / 128);
        gemm_mma_kernel<<<grid, 256, smem_bytes>>>(p_aqh, p_aql, p_bch, p_bcl,
                                                   p_bcat, p_logits, 256);
    }
    // ---- loc + softmax (outputs 2 & 3) ----
    {
        int total = NB * LQn * MH;
        postproc_kernel<<<(total + 255) / 256, 256>>>(refpts, p_logits, loc_out, attn_out);
    }
    // ---- deformable sampling -> g_tmp ----
    {
        int totalThreads = NB * LQn * MH * 32;
        sample_kernel<<<totalThreads / 256, 256>>>(loc_out, attn_out);
    }
    // ---- out = g_tmp @ W_out + b_out (output 1) ----
    {
        int n4 = NB * LQn * KK / 4;
        convA_kernel<<<(n4 + 255) / 256, 256>>>(p_tmp, p_ath, p_atl, n4);
        dim3 grid(256 / 128, (NB * LQn) / 128);
        gemm_mma_kernel<<<grid, 256, smem_bytes>>>(p_ath, p_atl, p_boh, p_bol,
                                                   b_out, out, 256);
    }
}

// round 9
// speedup vs baseline: 1.7646x; 1.1244x over previous
#include <cuda_runtime.h>
#include <cuda_bf16.h>
#include <cstdint>
#include <cstddef>

// Problem constants (static per reference)
#define NB  8
#define LQn 2048
#define CC  256
#define MH  8
#define LLv 4
#define DHd 32
#define SSt 3840
#define MLP 128   // M*L*P
#define KK  256   // GEMM K (= C)
#define NC  256   // GEMM N (all GEMMs are Nc=256 after fusion)

#define ASTR 40        // smem row stride in bf16 elems (80 B; 16B-aligned, conflict-free)
#define TILE_B (128 * ASTR * 2)   // 10240 B per 128x32 bf16 tile

// ---------------- scratch (__device__ globals; allocation-free rule) -------
__device__ float g_value [(size_t)NB * SSt * CC];   // value (N,S,M,DH) fp32
__device__ float g_logits[(size_t)NB * LQn * 256];  // [off(128) | attn(128)]
__device__ float g_loc2  [(size_t)NB * LQn * MLP];  // fallback outputs
__device__ float g_att2  [(size_t)NB * LQn * MLP];
__device__ float g_bcat  [256];

// bf16 hi/lo split activations (A matrices, row-major [R][256])
__device__ __nv_bfloat16 g_aih[(size_t)NB * SSt * KK];
__device__ __nv_bfloat16 g_ail[(size_t)NB * SSt * KK];
__device__ __nv_bfloat16 g_aqh[(size_t)NB * LQn * KK];
__device__ __nv_bfloat16 g_aql[(size_t)NB * LQn * KK];
__device__ __nv_bfloat16 g_ath[(size_t)NB * LQn * KK];
__device__ __nv_bfloat16 g_atl[(size_t)NB * LQn * KK];
// bf16 hi/lo transposed weights (B matrices, [Nc][256] K-major)
__device__ __nv_bfloat16 g_bvh[256 * KK], g_bvl[256 * KK];  // W_val^T
__device__ __nv_bfloat16 g_bch[256 * KK], g_bcl[256 * KK];  // [W_off|W_attn]^T
__device__ __nv_bfloat16 g_boh[256 * KK], g_bol[256 * KK];  // W_out^T

__device__ __forceinline__ uint32_t smem_u32(const void* p) {
    uint32_t a;
    asm("{ .reg .u64 t; cvta.to.shared.u64 t, %1; cvt.u32.u64 %0, t; }"
        : "=r"(a) : "l"(p));
    return a;
}

// ---------------------------------------------------------------------------
// mma.sync GEMM, dual-matrix dispatch: blocks [0,split) do matrix set 0,
// blocks [split, grid) do set 1. C[.,256] = (Ah+Al)(Bh+Bl)^T + bias,
// 3-term bf16 split, fp32 accumulate. CTA tile 128x128, 8 warps, BK=32,
// 2-stage cp.async pipeline. (Core identical to the validated round-5 GEMM.)
// ---------------------------------------------------------------------------
__global__ __launch_bounds__(256, 1)
void gemm_mma2_kernel(
    const __nv_bfloat16* __restrict__ Ah0, const __nv_bfloat16* __restrict__ Al0,
    const __nv_bfloat16* __restrict__ Bh0, const __nv_bfloat16* __restrict__ Bl0,
    const float* __restrict__ bias0, float* __restrict__ C0,
    const __nv_bfloat16* __restrict__ Ah1, const __nv_bfloat16* __restrict__ Al1,
    const __nv_bfloat16* __restrict__ Bh1, const __nv_bfloat16* __restrict__ Bl1,
    const float* __restrict__ bias1, float* __restrict__ C1,
    int split)
{
    extern __shared__ __align__(128) char smem[];
    uint32_t sb = smem_u32(smem);
    int tid  = threadIdx.x;
    int lane = tid & 31;
    int wid  = tid >> 5;
    int wr   = wid >> 2;     // 0..1  (m warp row)
    int wc   = wid & 3;      // 0..3  (n warp col)

    int bid = blockIdx.x;
    const __nv_bfloat16 *Ah, *Al, *Bh, *Bl;
    const float* bias;
    float* Cmat;
    int local;
    if (bid < split) {
        Ah = Ah0; Al = Al0; Bh = Bh0; Bl = Bl0; bias = bias0; Cmat = C0;
        local = bid;
    } else {
        Ah = Ah1; Al = Al1; Bh = Bh1; Bl = Bl1; bias = bias1; Cmat = C1;
        local = bid - split;
    }
    int bm = (local >> 1) * 128;
    int bn = (local & 1) * 128;

    const __nv_bfloat16* gtab[4] = {Ah + (size_t)bm * KK, Al + (size_t)bm * KK,
                                    Bh + (size_t)bn * KK, Bl + (size_t)bn * KK};
    int srow  = tid >> 1;          // 0..127
    int sboff = (tid & 1) * 32;    // 0 or 32 bytes within 64B row chunk

    float acc[4][4][4];
    #pragma unroll
    for (int i = 0; i < 4; i++)
        #pragma unroll
        for (int j = 0; j < 4; j++)
            #pragma unroll
            for (int r = 0; r < 4; r++) acc[i][j][r] = 0.f;

    int a_r = lane & 15;
    int a_k = (lane >> 4) << 3;
    int b_r = lane & 7;
    int b_k = ((lane >> 3) & 1) << 3;

    #define STAGE_LOAD(s, k0) do {                                              \
        _Pragma("unroll")                                                       \
        for (int t = 0; t < 4; t++) {                                           \
            uint32_t sdst = sb + (uint32_t)((s) * 4 + t) * TILE_B               \
                          + (uint32_t)srow * (ASTR * 2) + sboff;                \
            const char* gsrc = (const char*)(gtab[t] + (size_t)srow * KK + (k0))\
                             + sboff;                                           \
            asm volatile("cp.async.cg.shared.global [%0], [%1], 16;"            \
                         :: "r"(sdst), "l"(gsrc));                              \
            asm volatile("cp.async.cg.shared.global [%0], [%1], 16;"            \
                         :: "r"(sdst + 16), "l"(gsrc + 16));                    \
        }                                                                       \
        asm volatile("cp.async.commit_group;" ::: "memory");                    \
    } while (0)

    STAGE_LOAD(0, 0);

    for (int kt = 0; kt < 8; kt++) {
        if (kt < 7) {
            STAGE_LOAD((kt + 1) & 1, (kt + 1) * 32);
            asm volatile("cp.async.wait_group 1;" ::: "memory");
        } else {
            asm volatile("cp.async.wait_group 0;" ::: "memory");
        }
        __syncthreads();

        int s = kt & 1;
        uint32_t sAh = sb + (uint32_t)(s * 4 + 0) * TILE_B;
        uint32_t sAl = sb + (uint32_t)(s * 4 + 1) * TILE_B;
        uint32_t sBh = sb + (uint32_t)(s * 4 + 2) * TILE_B;
        uint32_t sBl = sb + (uint32_t)(s * 4 + 3) * TILE_B;

        #pragma unroll
        for (int kk = 0; kk < 32; kk += 16) {
            uint32_t ah[4][4], al[4][4], bh[4][2], bl[4][2];
            #pragma unroll
            for (int mi = 0; mi < 4; mi++) {
                int row = wr * 64 + mi * 16 + a_r;
                uint32_t off = (uint32_t)(row * ASTR + kk + a_k) * 2;
                asm volatile(
                    "ldmatrix.sync.aligned.m8n8.x4.shared.b16 {%0,%1,%2,%3}, [%4];"
                    : "=r"(ah[mi][0]), "=r"(ah[mi][1]), "=r"(ah[mi][2]), "=r"(ah[mi][3])
                    : "r"(sAh + off));
                asm volatile(
                    "ldmatrix.sync.aligned.m8n8.x4.shared.b16 {%0,%1,%2,%3}, [%4];"
                    : "=r"(al[mi][0]), "=r"(al[mi][1]), "=r"(al[mi][2]), "=r"(al[mi][3])
                    : "r"(sAl + off));
            }
            #pragma unroll
            for (int ni = 0; ni < 4; ni++) {
                int row = wc * 32 + ni * 8 + b_r;
                uint32_t off = (uint32_t)(row * ASTR + kk + b_k) * 2;
                asm volatile(
                    "ldmatrix.sync.aligned.m8n8.x2.shared.b16 {%0,%1}, [%2];"
                    : "=r"(bh[ni][0]), "=r"(bh[ni][1]) : "r"(sBh + off));
                asm volatile(
                    "ldmatrix.sync.aligned.m8n8.x2.shared.b16 {%0,%1}, [%2];"
                    : "=r"(bl[ni][0]), "=r"(bl[ni][1]) : "r"(sBl + off));
            }

            #define MMA(ACC, A, B)                                              \
                asm volatile(                                                   \
                    "mma.sync.aligned.m16n8k16.row.col.f32.bf16.bf16.f32 "      \
                    "{%0,%1,%2,%3}, {%4,%5,%6,%7}, {%8,%9}, {%0,%1,%2,%3};"     \
                    : "+f"((ACC)[0]), "+f"((ACC)[1]), "+f"((ACC)[2]), "+f"((ACC)[3]) \
                    : "r"((A)[0]), "r"((A)[1]), "r"((A)[2]), "r"((A)[3]),       \
                      "r"((B)[0]), "r"((B)[1]))

            #pragma unroll
            for (int mi = 0; mi < 4; mi++)
                #pragma unroll
                for (int ni = 0; ni < 4; ni++) {
                    MMA(acc[mi][ni], ah[mi], bh[ni]);   // Ah*Bh
                    MMA(acc[mi][ni], al[mi], bh[ni]);   // Al*Bh
                    MMA(acc[mi][ni], ah[mi], bl[ni]);   // Ah*Bl
                }
            #undef MMA
        }
        __syncthreads();
    }
    #undef STAGE_LOAD

    // ---- epilogue: fp32 + bias ----
    int r0 = bm + wr * 64;
    int c0 = bn + wc * 32;
    #pragma unroll
    for (int mi = 0; mi < 4; mi++) {
        int row = r0 + mi * 16 + (lane >> 2);
        #pragma unroll
        for (int ni = 0; ni < 4; ni++) {
            int col = c0 + ni * 8 + (lane & 3) * 2;
            float2 bv = *(const float2*)(bias + col);
            float2 v0 = {acc[mi][ni][0] + bv.x, acc[mi][ni][1] + bv.y};
            float2 v1 = {acc[mi][ni][2] + bv.x, acc[mi][ni][3] + bv.y};
            *(float2*)(Cmat + (size_t)row * NC + col)       = v0;
            *(float2*)(Cmat + (size_t)(row + 8) * NC + col) = v1;
        }
    }
}

// ---------------------------------------------------------------------------
// Weight prep (one launch): three W^T hi/lo conversions + bias concat
// idx [0,64K): W_val ; [64K,128K): [W_off|W_attn] ; [128K,192K): W_out ;
// [192K,192K+256): bcat
// ---------------------------------------------------------------------------
__global__ __launch_bounds__(256) void prep_kernel(
    const float* __restrict__ W_val, const float* __restrict__ W_off,
    const float* __restrict__ W_attn, const float* __restrict__ W_out,
    const float* __restrict__ b_off, const float* __restrict__ b_attn,
    __nv_bfloat16* __restrict__ bvh, __nv_bfloat16* __restrict__ bvl,
    __nv_bfloat16* __restrict__ bch, __nv_bfloat16* __restrict__ bcl,
    __nv_bfloat16* __restrict__ boh, __nv_bfloat16* __restrict__ bol,
    float* __restrict__ bcat)
{
    int gid = blockIdx.x * blockDim.x + threadIdx.x;
    if (gid >= 3 * 65536) {
        int i = gid - 3 * 65536;
        if (i < 256) bcat[i] = (i < 128) ? b_off[i] : b_attn[i - 128];
        return;
    }
    int which = gid >> 16;
    int idx   = gid & 65535;
    int n = idx >> 8, k = idx & 255;
    float v;
    __nv_bfloat16 *dh, *dl;
    if (which == 0) {
        v = W_val[(size_t)k * 256 + n]; dh = bvh; dl = bvl;
    } else if (which == 1) {
        v = (n < 128) ? W_off[(size_t)k * 128 + n]
                      : W_attn[(size_t)k * 128 + (n - 128)];
        dh = bch; dl = bcl;
    } else {
        v = W_out[(size_t)k * 256 + n]; dh = boh; dl = bol;
    }
    __nv_bfloat16 h = __float2bfloat16(v);
    dh[idx] = h;
    dl[idx] = __float2bfloat16(v - __bfloat162float(h));
}

// ---------------------------------------------------------------------------
// fp32 -> bf16 hi/lo split for BOTH inp and query in one launch
// ---------------------------------------------------------------------------
__global__ __launch_bounds__(256) void conv2_kernel(
    const float* __restrict__ s0, __nv_bfloat16* __restrict__ h0,
    __nv_bfloat16* __restrict__ l0, int n40,
    const float* __restrict__ s1, __nv_bfloat16* __restrict__ h1,
    __nv_bfloat16* __restrict__ l1, int n41)
{
    int i = blockIdx.x * blockDim.x + threadIdx.x;
    const float* s; __nv_bfloat16 *H8, *L8; int j;
    if (i < n40) { s = s0; H8 = h0; L8 = l0; j = i; }
    else {
        j = i - n40;
        if (j >= n41) return;
        s = s1; H8 = h1; L8 = l1;
    }
    float4 v = ((const float4*)s)[j];
    __nv_bfloat16 a0 = __float2bfloat16(v.x), a1 = __float2bfloat16(v.y);
    __nv_bfloat16 a2 = __float2bfloat16(v.z), a3 = __float2bfloat16(v.w);
    __nv_bfloat16 c0 = __float2bfloat16(v.x - __bfloat162float(a0));
    __nv_bfloat16 c1 = __float2bfloat16(v.y - __bfloat162float(a1));
    __nv_bfloat16 c2 = __float2bfloat16(v.z - __bfloat162float(a2));
    __nv_bfloat16 c3 = __float2bfloat16(v.w - __bfloat162float(a3));
    __nv_bfloat162* H = (__nv_bfloat162*)H8;
    __nv_bfloat162* L = (__nv_bfloat162*)L8;
    H[2 * j]     = __nv_bfloat162(a0, a1);
    H[2 * j + 1] = __nv_bfloat162(a2, a3);
    L[2 * j]     = __nv_bfloat162(c0, c1);
    L[2 * j + 1] = __nv_bfloat162(c2, c3);
}

// ---------------------------------------------------------------------------
// Fused postproc + sampling. Warp per (n,q,m); lanes 0-15 own one (l,p) each
// for softmax/loc (dup on 16-31); all 32 lanes are channels for sampling.
// Writes loc/attn outputs AND bf16 hi/lo sampled features (A of out-GEMM).
// ---------------------------------------------------------------------------
__global__ __launch_bounds__(256) void sample_fused_kernel(
    const float* __restrict__ refpts, const float* __restrict__ logits,
    float* __restrict__ loc_out, float* __restrict__ attn_out,
    __nv_bfloat16* __restrict__ outh, __nv_bfloat16* __restrict__ outl)
{
    int gwarp = (blockIdx.x * blockDim.x + threadIdx.x) >> 5;
    int lane  = threadIdx.x & 31;
    if (gwarp >= NB * LQn * MH) return;
    int m  = gwarp & 7;
    int nq = gwarp >> 3;
    int n  = nq >> 11;                 // / LQn

    // --- softmax + loc on 16 logical slots (duplicated across half-warps) ---
    int li = lane & 15;
    const float* lrow = logits + (size_t)nq * 256 + m * 16;
    float offv = lrow[li];
    float lgv  = lrow[128 + li];
    float mx = lgv;
    #pragma unroll
    for (int d = 1; d < 16; d <<= 1)
        mx = fmaxf(mx, __shfl_xor_sync(0xffffffffu, mx, d));
    float ev = __expf(lgv - mx);
    float sum = ev;
    #pragma unroll
    for (int d = 1; d < 16; d <<= 1)
        sum += __shfl_xor_sync(0xffffffffu, sum, d);
    float attnv = ev / sum;

    const float innorm[4] = {1.f / 2048.f, 1.f / 1024.f, 1.f / 512.f, 1.f / 256.f};
    int lv = li >> 2;
    float rn = refpts[(size_t)nq * 4 + lv];
    float locv = rn + offv * innorm[lv];

    if (lane < 16) {
        loc_out [(size_t)gwarp * 16 + lane] = locv;
        attn_out[(size_t)gwarp * 16 + lane] = attnv;
    }

    // --- sampling: lane = channel ---
    const int lens[4]   = {2048, 1024, 512, 256};
    const int starts[4] = {0, 2048, 3072, 3584};
    float acc = 0.f;
    #pragma unroll
    for (int i = 0; i < 16; i++) {
        float a  = __shfl_sync(0xffffffffu, attnv, i);
        float lc = __shfl_sync(0xffffffffu, locv, i);
        int lev = i >> 2;
        int T = lens[lev], st = starts[lev];
        const float* vbase = g_value + ((((size_t)n * SSt + st) * MH + m) * DHd) + lane;
        float pos = lc * (float)T - 0.5f;
        float x0f = floorf(pos);
        float frac = pos - x0f;
        int x0 = (int)x0f;
        float w0 = (x0 >= 0 && x0 < T)         ? (1.f - frac) : 0.f;
        float w1 = (x0 + 1 >= 0 && x0 + 1 < T) ? frac         : 0.f;
        int i0 = min(max(x0, 0), T - 1);
        int i1 = min(max(x0 + 1, 0), T - 1);
        float v0 = vbase[(size_t)i0 * (MH * DHd)];
        float v1 = vbase[(size_t)i1 * (MH * DHd)];
        acc += a * (w0 * v0 + w1 * v1);
    }

    __nv_bfloat16 h = __float2bfloat16(acc);
    size_t oidx = (size_t)gwarp * DHd + lane;
    outh[oidx] = h;
    outl[oidx] = __float2bfloat16(acc - __bfloat162float(h));
}

// ---------------------------------------------------------------------------
extern "C" void kernel_launch(void* const* d_in, const int* in_sizes, int n_in,
                              void* d_out, int out_size)
{
    const float* query  = (const float*)d_in[0];
    const float* refpts = (const float*)d_in[1];
    const float* inp    = (const float*)d_in[2];
    const float* W_off  = (const float*)d_in[5];
    const float* b_off  = (const float*)d_in[6];
    const float* W_attn = (const float*)d_in[7];
    const float* b_attn = (const float*)d_in[8];
    const float* W_val  = (const float*)d_in[9];
    const float* b_val  = (const float*)d_in[10];
    const float* W_out  = (const float*)d_in[11];
    const float* b_out  = (const float*)d_in[12];
    float* out = (float*)d_out;

    float *p_value, *p_logits, *p_loc2, *p_att2, *p_bcat;
    __nv_bfloat16 *p_aih, *p_ail, *p_aqh, *p_aql, *p_ath, *p_atl;
    __nv_bfloat16 *p_bvh, *p_bvl, *p_bch, *p_bcl, *p_boh, *p_bol;
    cudaGetSymbolAddress((void**)&p_value,  g_value);
    cudaGetSymbolAddress((void**)&p_logits, g_logits);
    cudaGetSymbolAddress((void**)&p_loc2,   g_loc2);
    cudaGetSymbolAddress((void**)&p_att2,   g_att2);
    cudaGetSymbolAddress((void**)&p_bcat,   g_bcat);
    cudaGetSymbolAddress((void**)&p_aih, g_aih);  cudaGetSymbolAddress((void**)&p_ail, g_ail);
    cudaGetSymbolAddress((void**)&p_aqh, g_aqh);  cudaGetSymbolAddress((void**)&p_aql, g_aql);
    cudaGetSymbolAddress((void**)&p_ath, g_ath);  cudaGetSymbolAddress((void**)&p_atl, g_atl);
    cudaGetSymbolAddress((void**)&p_bvh, g_bvh);  cudaGetSymbolAddress((void**)&p_bvl, g_bvl);
    cudaGetSymbolAddress((void**)&p_bch, g_bch);  cudaGetSymbolAddress((void**)&p_bcl, g_bcl);
    cudaGetSymbolAddress((void**)&p_boh, g_boh);  cudaGetSymbolAddress((void**)&p_bol, g_bol);

    const int out_elems = NB * LQn * CC;        // 4194304
    const int locattn   = NB * LQn * MLP;       // 1048576
    bool full_out = (out_size >= out_elems + 2 * locattn);
    float* loc_out  = full_out ? (out + out_elems)           : p_loc2;
    float* attn_out = full_out ? (out + out_elems + locattn) : p_att2;

    const int smem_bytes = 8 * TILE_B;          // 81920
    cudaFuncSetAttribute(gemm_mma2_kernel,
                         cudaFuncAttributeMaxDynamicSharedMemorySize, smem_bytes);

    // ---- 1) weight prep + bias concat (one launch) ----
    {
        int total = 3 * 65536 + 256;
        prep_kernel<<<(total + 255) / 256, 256>>>(
            W_val, W_off, W_attn, W_out, b_off, b_attn,
            p_bvh, p_bvl, p_bch, p_bcl, p_boh, p_bol, p_bcat);
    }
    // ---- 2) activation hi/lo conversion: inp + query (one launch) ----
    {
        int n40 = NB * SSt * KK / 4;            // 1966080
        int n41 = NB * LQn * KK / 4;            // 1048576
        conv2_kernel<<<(n40 + n41 + 255) / 256, 256>>>(
            inp, p_aih, p_ail, n40, query, p_aqh, p_aql, n41);
    }
    // ---- 3) value GEMM (480 tiles) + logits GEMM (256 tiles), one launch ----
    {
        int split = (NB * SSt / 128) * 2;       // 480
        int total = split + (NB * LQn / 128) * 2;   // 736
        gemm_mma2_kernel<<<total, 256, smem_bytes>>>(
            p_aih, p_ail, p_bvh, p_bvl, b_val,  p_value,
            p_aqh, p_aql, p_bch, p_bcl, p_bcat, p_logits,
            split);
    }
    // ---- 4) fused postproc + sampling (outputs 2&3 + bf16 A for out-GEMM) ----
    {
        int totalThreads = NB * LQn * MH * 32;
        sample_fused_kernel<<<totalThreads / 256, 256>>>(
            refpts, p_logits, loc_out, attn_out, p_ath, p_atl);
    }
    // ---- 5) out = sampled @ W_out + b_out (output 1) ----
    {
        int total = (NB * LQn / 128) * 2;       // 256
        gemm_mma2_kernel<<<total, 256, smem_bytes>>>(
            p_ath, p_atl, p_boh, p_bol, b_out, out,
            p_ath, p_atl, p_boh, p_bol, b_out, out,
            total);
    }
}

// round 11
// speedup vs baseline: 1.9498x; 1.1050x over previous
#include <cuda_runtime.h>
#include <cuda_bf16.h>
#include <cstdint>
#include <cstddef>

// Problem constants (static per reference)
#define NB  8
#define LQn 2048
#define CC  256
#define MH  8
#define LLv 4
#define DHd 32
#define SSt 3840
#define MLP 128   // M*L*P
#define KK  256   // GEMM K (= C)
#define NC  256   // GEMM N (all GEMMs are Nc=256 after fusion)

#define ASTR 40        // smem row stride in bf16 elems (80 B; 16B-aligned, conflict-free)
#define TILE_B (128 * ASTR * 2)   // 10240 B per 128x32 bf16 tile

// ---------------- scratch (__device__ globals; allocation-free rule) -------
__device__ float g_value [(size_t)NB * SSt * CC];   // value (N,S,M,DH) fp32
__device__ float g_logits[(size_t)NB * LQn * 256];  // [off(128) | attn(128)]
__device__ float g_loc2  [(size_t)NB * LQn * MLP];  // fallback outputs
__device__ float g_att2  [(size_t)NB * LQn * MLP];
__device__ float g_bcat  [256];

// bf16 hi/lo split activations (A matrices, row-major [R][256])
__device__ __nv_bfloat16 g_aih[(size_t)NB * SSt * KK];
__device__ __nv_bfloat16 g_ail[(size_t)NB * SSt * KK];
__device__ __nv_bfloat16 g_aqh[(size_t)NB * LQn * KK];
__device__ __nv_bfloat16 g_aql[(size_t)NB * LQn * KK];
__device__ __nv_bfloat16 g_ath[(size_t)NB * LQn * KK];
__device__ __nv_bfloat16 g_atl[(size_t)NB * LQn * KK];
// bf16 hi/lo transposed weights (B matrices, [Nc][256] K-major)
__device__ __nv_bfloat16 g_bvh[256 * KK], g_bvl[256 * KK];  // W_val^T
__device__ __nv_bfloat16 g_bch[256 * KK], g_bcl[256 * KK];  // [W_off|W_attn]^T
__device__ __nv_bfloat16 g_boh[256 * KK], g_bol[256 * KK];  // W_out^T

__device__ __forceinline__ uint32_t smem_u32(const void* p) {
    uint32_t a;
    asm("{ .reg .u64 t; cvta.to.shared.u64 t, %1; cvt.u32.u64 %0, t; }"
        : "=r"(a) : "l"(p));
    return a;
}

// ---------------------------------------------------------------------------
// mma.sync GEMM, dual-matrix dispatch: blocks [0,split) do matrix set 0,
// blocks [split, grid) do set 1. C[.,256] = (Ah+Al)(Bh+Bl)^T + bias,
// 3-term bf16 split, fp32 accumulate. CTA tile 128x128, 8 warps, BK=32,
// 2-stage cp.async pipeline. (Core identical to the validated round-5 GEMM.)
// ---------------------------------------------------------------------------
__global__ __launch_bounds__(256, 1)
void gemm_mma2_kernel(
    const __nv_bfloat16* __restrict__ Ah0, const __nv_bfloat16* __restrict__ Al0,
    const __nv_bfloat16* __restrict__ Bh0, const __nv_bfloat16* __restrict__ Bl0,
    const float* __restrict__ bias0, float* __restrict__ C0,
    const __nv_bfloat16* __restrict__ Ah1, const __nv_bfloat16* __restrict__ Al1,
    const __nv_bfloat16* __restrict__ Bh1, const __nv_bfloat16* __restrict__ Bl1,
    const float* __restrict__ bias1, float* __restrict__ C1,
    int split)
{
    extern __shared__ __align__(128) char smem[];
    uint32_t sb = smem_u32(smem);
    int tid  = threadIdx.x;
    int lane = tid & 31;
    int wid  = tid >> 5;
    int wr   = wid >> 2;     // 0..1  (m warp row)
    int wc   = wid & 3;      // 0..3  (n warp col)

    int bid = blockIdx.x;
    const __nv_bfloat16 *Ah, *Al, *Bh, *Bl;
    const float* bias;
    float* Cmat;
    int local;
    if (bid < split) {
        Ah = Ah0; Al = Al0; Bh = Bh0; Bl = Bl0; bias = bias0; Cmat = C0;
        local = bid;
    } else {
        Ah = Ah1; Al = Al1; Bh = Bh1; Bl = Bl1; bias = bias1; Cmat = C1;
        local = bid - split;
    }
    int bm = (local >> 1) * 128;
    int bn = (local & 1) * 128;

    const __nv_bfloat16* gtab[4] = {Ah + (size_t)bm * KK, Al + (size_t)bm * KK,
                                    Bh + (size_t)bn * KK, Bl + (size_t)bn * KK};
    int srow  = tid >> 1;          // 0..127
    int sboff = (tid & 1) * 32;    // 0 or 32 bytes within 64B row chunk

    float acc[4][4][4];
    #pragma unroll
    for (int i = 0; i < 4; i++)
        #pragma unroll
        for (int j = 0; j < 4; j++)
            #pragma unroll
            for (int r = 0; r < 4; r++) acc[i][j][r] = 0.f;

    int a_r = lane & 15;
    int a_k = (lane >> 4) << 3;
    int b_r = lane & 7;
    int b_k = ((lane >> 3) & 1) << 3;

    #define STAGE_LOAD(s, k0) do {                                              \
        _Pragma("unroll")                                                       \
        for (int t = 0; t < 4; t++) {                                           \
            uint32_t sdst = sb + (uint32_t)((s) * 4 + t) * TILE_B               \
                          + (uint32_t)srow * (ASTR * 2) + sboff;                \
            const char* gsrc = (const char*)(gtab[t] + (size_t)srow * KK + (k0))\
                             + sboff;                                           \
            asm volatile("cp.async.cg.shared.global [%0], [%1], 16;"            \
                         :: "r"(sdst), "l"(gsrc));                              \
            asm volatile("cp.async.cg.shared.global [%0], [%1], 16;"            \
                         :: "r"(sdst + 16), "l"(gsrc + 16));                    \
        }                                                                       \
        asm volatile("cp.async.commit_group;" ::: "memory");                    \
    } while (0)

    STAGE_LOAD(0, 0);

    for (int kt = 0; kt < 8; kt++) {
        if (kt < 7) {
            STAGE_LOAD((kt + 1) & 1, (kt + 1) * 32);
            asm volatile("cp.async.wait_group 1;" ::: "memory");
        } else {
            asm volatile("cp.async.wait_group 0;" ::: "memory");
        }
        __syncthreads();

        int s = kt & 1;
        uint32_t sAh = sb + (uint32_t)(s * 4 + 0) * TILE_B;
        uint32_t sAl = sb + (uint32_t)(s * 4 + 1) * TILE_B;
        uint32_t sBh = sb + (uint32_t)(s * 4 + 2) * TILE_B;
        uint32_t sBl = sb + (uint32_t)(s * 4 + 3) * TILE_B;

        #pragma unroll
        for (int kk = 0; kk < 32; kk += 16) {
            uint32_t ah[4][4], al[4][4], bh[4][2], bl[4][2];
            #pragma unroll
            for (int mi = 0; mi < 4; mi++) {
                int row = wr * 64 + mi * 16 + a_r;
                uint32_t off = (uint32_t)(row * ASTR + kk + a_k) * 2;
                asm volatile(
                    "ldmatrix.sync.aligned.m8n8.x4.shared.b16 {%0,%1,%2,%3}, [%4];"
                    : "=r"(ah[mi][0]), "=r"(ah[mi][1]), "=r"(ah[mi][2]), "=r"(ah[mi][3])
                    : "r"(sAh + off));
                asm volatile(
                    "ldmatrix.sync.aligned.m8n8.x4.shared.b16 {%0,%1,%2,%3}, [%4];"
                    : "=r"(al[mi][0]), "=r"(al[mi][1]), "=r"(al[mi][2]), "=r"(al[mi][3])
                    : "r"(sAl + off));
            }
            #pragma unroll
            for (int ni = 0; ni < 4; ni++) {
                int row = wc * 32 + ni * 8 + b_r;
                uint32_t off = (uint32_t)(row * ASTR + kk + b_k) * 2;
                asm volatile(
                    "ldmatrix.sync.aligned.m8n8.x2.shared.b16 {%0,%1}, [%2];"
                    : "=r"(bh[ni][0]), "=r"(bh[ni][1]) : "r"(sBh + off));
                asm volatile(
                    "ldmatrix.sync.aligned.m8n8.x2.shared.b16 {%0,%1}, [%2];"
                    : "=r"(bl[ni][0]), "=r"(bl[ni][1]) : "r"(sBl + off));
            }

            #define MMA(ACC, A, B)                                              \
                asm volatile(                                                   \
                    "mma.sync.aligned.m16n8k16.row.col.f32.bf16.bf16.f32 "      \
                    "{%0,%1,%2,%3}, {%4,%5,%6,%7}, {%8,%9}, {%0,%1,%2,%3};"     \
                    : "+f"((ACC)[0]), "+f"((ACC)[1]), "+f"((ACC)[2]), "+f"((ACC)[3]) \
                    : "r"((A)[0]), "r"((A)[1]), "r"((A)[2]), "r"((A)[3]),       \
                      "r"((B)[0]), "r"((B)[1]))

            #pragma unroll
            for (int mi = 0; mi < 4; mi++)
                #pragma unroll
                for (int ni = 0; ni < 4; ni++) {
                    MMA(acc[mi][ni], ah[mi], bh[ni]);   // Ah*Bh
                    MMA(acc[mi][ni], al[mi], bh[ni]);   // Al*Bh
                    MMA(acc[mi][ni], ah[mi], bl[ni]);   // Ah*Bl
                }
            #undef MMA
        }
        __syncthreads();
    }
    #undef STAGE_LOAD

    // ---- epilogue: fp32 + bias ----
    int r0 = bm + wr * 64;
    int c0 = bn + wc * 32;
    #pragma unroll
    for (int mi = 0; mi < 4; mi++) {
        int row = r0 + mi * 16 + (lane >> 2);
        #pragma unroll
        for (int ni = 0; ni < 4; ni++) {
            int col = c0 + ni * 8 + (lane & 3) * 2;
            float2 bv = *(const float2*)(bias + col);
            float2 v0 = {acc[mi][ni][0] + bv.x, acc[mi][ni][1] + bv.y};
            float2 v1 = {acc[mi][ni][2] + bv.x, acc[mi][ni][3] + bv.y};
            *(float2*)(Cmat + (size_t)row * NC + col)       = v0;
            *(float2*)(Cmat + (size_t)(row + 8) * NC + col) = v1;
        }
    }
}

// ---------------------------------------------------------------------------
// Combined prep + activation conversion (one launch).
// Blocks [0, PREP_BLKS): weight W^T hi/lo conversions + bias concat.
// Blocks [PREP_BLKS, ...): fp32 -> bf16 hi/lo split of inp and query.
// ---------------------------------------------------------------------------
#define PREP_ITEMS (3 * 65536 + 256)
#define PREP_BLKS  ((PREP_ITEMS + 255) / 256)

__global__ __launch_bounds__(256) void prepconv_kernel(
    const float* __restrict__ W_val, const float* __restrict__ W_off,
    const float* __restrict__ W_attn, const float* __restrict__ W_out,
    const float* __restrict__ b_off, const float* __restrict__ b_attn,
    __nv_bfloat16* __restrict__ bvh, __nv_bfloat16* __restrict__ bvl,
    __nv_bfloat16* __restrict__ bch, __nv_bfloat16* __restrict__ bcl,
    __nv_bfloat16* __restrict__ boh, __nv_bfloat16* __restrict__ bol,
    float* __restrict__ bcat,
    const float* __restrict__ s0, __nv_bfloat16* __restrict__ h0,
    __nv_bfloat16* __restrict__ l0, int n40,
    const float* __restrict__ s1, __nv_bfloat16* __restrict__ h1,
    __nv_bfloat16* __restrict__ l1, int n41)
{
    if (blockIdx.x < PREP_BLKS) {
        int gid = blockIdx.x * 256 + threadIdx.x;
        if (gid >= 3 * 65536) {
            int i = gid - 3 * 65536;
            if (i < 256) bcat[i] = (i < 128) ? b_off[i] : b_attn[i - 128];
            return;
        }
        int which = gid >> 16;
        int idx   = gid & 65535;
        int n = idx >> 8, k = idx & 255;
        float v;
        __nv_bfloat16 *dh, *dl;
        if (which == 0) {
            v = W_val[(size_t)k * 256 + n]; dh = bvh; dl = bvl;
        } else if (which == 1) {
            v = (n < 128) ? W_off[(size_t)k * 128 + n]
                          : W_attn[(size_t)k * 128 + (n - 128)];
            dh = bch; dl = bcl;
        } else {
            v = W_out[(size_t)k * 256 + n]; dh = boh; dl = bol;
        }
        __nv_bfloat16 h = __float2bfloat16(v);
        dh[idx] = h;
        dl[idx] = __float2bfloat16(v - __bfloat162float(h));
        return;
    }

    int i = (blockIdx.x - PREP_BLKS) * 256 + threadIdx.x;
    const float* s; __nv_bfloat16 *H8, *L8; int j;
    if (i < n40) { s = s0; H8 = h0; L8 = l0; j = i; }
    else {
        j = i - n40;
        if (j >= n41) return;
        s = s1; H8 = h1; L8 = l1;
    }
    float4 v = ((const float4*)s)[j];
    __nv_bfloat16 a0 = __float2bfloat16(v.x), a1 = __float2bfloat16(v.y);
    __nv_bfloat16 a2 = __float2bfloat16(v.z), a3 = __float2bfloat16(v.w);
    __nv_bfloat16 c0 = __float2bfloat16(v.x - __bfloat162float(a0));
    __nv_bfloat16 c1 = __float2bfloat16(v.y - __bfloat162float(a1));
    __nv_bfloat16 c2 = __float2bfloat16(v.z - __bfloat162float(a2));
    __nv_bfloat16 c3 = __float2bfloat16(v.w - __bfloat162float(a3));
    __nv_bfloat162* H = (__nv_bfloat162*)H8;
    __nv_bfloat162* L = (__nv_bfloat162*)L8;
    H[2 * j]     = __nv_bfloat162(a0, a1);
    H[2 * j + 1] = __nv_bfloat162(a2, a3);
    L[2 * j]     = __nv_bfloat162(c0, c1);
    L[2 * j + 1] = __nv_bfloat162(c2, c3);
}

// ---------------------------------------------------------------------------
// Fused postproc + sampling. Warp per (n,q,m); lanes 0-15 own one (l,p) slot
// (softmax, loc, bilinear setup hoisted); the gather loop is 3 shfl + 2 LDG
// + 2 FFMA per point. All 32-bit indexing.
// ---------------------------------------------------------------------------
__global__ __launch_bounds__(256) void sample_fused_kernel(
    const float* __restrict__ refpts, const float* __restrict__ logits,
    float* __restrict__ loc_out, float* __restrict__ attn_out,
    __nv_bfloat16* __restrict__ outh, __nv_bfloat16* __restrict__ outl)
{
    int gwarp = blockIdx.x * 8 + (threadIdx.x >> 5);   // (n,q,m), < 131072
    int lane  = threadIdx.x & 31;
    int m  = gwarp & 7;
    int nq = gwarp >> 3;
    int n  = nq >> 11;                 // / LQn

    // --- softmax + loc on 16 slots (owner lanes 0-15; 16-31 mirror) ---
    int li = lane & 15;
    const float* lrow = logits + nq * 256 + m * 16;
    float offv = lrow[li];
    float lgv  = lrow[128 + li];
    float mx = lgv;
    #pragma unroll
    for (int d = 1; d < 16; d <<= 1)
        mx = fmaxf(mx, __shfl_xor_sync(0xffffffffu, mx, d));
    float ev = __expf(lgv - mx);
    float sum = ev;
    #pragma unroll
    for (int d = 1; d < 16; d <<= 1)
        sum += __shfl_xor_sync(0xffffffffu, sum, d);
    float attnv = ev / sum;

    const float innorm[4] = {1.f / 2048.f, 1.f / 1024.f, 1.f / 512.f, 1.f / 256.f};
    int lv = li >> 2;
    float rn = refpts[nq * 4 + lv];
    float locv = rn + offv * innorm[lv];

    if (lane < 16) {
        loc_out [gwarp * 16 + lane] = locv;
        attn_out[gwarp * 16 + lane] = attnv;
    }

    // --- per-slot bilinear setup (once, in owner lanes) ---
    const int lens[4]   = {2048, 1024, 512, 256};
    const int starts[4] = {0, 2048, 3072, 3584};
    int T = lens[lv], st = starts[lv];
    float pos = locv * (float)T - 0.5f;
    float x0f = floorf(pos);
    float frac = pos - x0f;
    int x0 = (int)x0f;
    float w0 = (x0 >= 0 && x0 < T)         ? (1.f - frac) : 0.f;
    float w1 = (x0 + 1 >= 0 && x0 + 1 < T) ? frac         : 0.f;
    float aw0 = attnv * w0;
    float aw1 = attnv * w1;
    int i0 = min(max(x0, 0), T - 1) + st;       // absolute row in [0, 3840)
    int i1 = min(max(x0 + 1, 0), T - 1) + st;
    int packed = i0 | (i1 << 16);

    // --- gather: lane = channel ---
    const float* vbase = g_value + (n * SSt * CC + m * DHd + lane);
    float acc = 0.f;
    #pragma unroll
    for (int i = 0; i < 16; i++) {
        float a0 = __shfl_sync(0xffffffffu, aw0, i);
        float a1 = __shfl_sync(0xffffffffu, aw1, i);
        int   pk = __shfl_sync(0xffffffffu, packed, i);
        int o0 = (pk & 0xFFFF) << 8;            // row * 256 floats
        int o1 = ((unsigned)pk >> 16) << 8;
        acc += a0 * vbase[o0] + a1 * vbase[o1];
    }

    __nv_bfloat16 h = __float2bfloat16(acc);
    int oidx = gwarp * DHd + lane;
    outh[oidx] = h;
    outl[oidx] = __float2bfloat16(acc - __bfloat162float(h));
}

// ---------------------------------------------------------------------------
extern "C" void kernel_launch(void* const* d_in, const int* in_sizes, int n_in,
                              void* d_out, int out_size)
{
    const float* query  = (const float*)d_in[0];
    const float* refpts = (const float*)d_in[1];
    const float* inp    = (const float*)d_in[2];
    const float* W_off  = (const float*)d_in[5];
    const float* b_off  = (const float*)d_in[6];
    const float* W_attn = (const float*)d_in[7];
    const float* b_attn = (const float*)d_in[8];
    const float* W_val  = (const float*)d_in[9];
    const float* b_val  = (const float*)d_in[10];
    const float* W_out  = (const float*)d_in[11];
    const float* b_out  = (const float*)d_in[12];
    float* out = (float*)d_out;

    float *p_value, *p_logits, *p_loc2, *p_att2, *p_bcat;
    __nv_bfloat16 *p_aih, *p_ail, *p_aqh, *p_aql, *p_ath, *p_atl;
    __nv_bfloat16 *p_bvh, *p_bvl, *p_bch, *p_bcl, *p_boh, *p_bol;
    cudaGetSymbolAddress((void**)&p_value,  g_value);
    cudaGetSymbolAddress((void**)&p_logits, g_logits);
    cudaGetSymbolAddress((void**)&p_loc2,   g_loc2);
    cudaGetSymbolAddress((void**)&p_att2,   g_att2);
    cudaGetSymbolAddress((void**)&p_bcat,   g_bcat);
    cudaGetSymbolAddress((void**)&p_aih, g_aih);  cudaGetSymbolAddress((void**)&p_ail, g_ail);
    cudaGetSymbolAddress((void**)&p_aqh, g_aqh);  cudaGetSymbolAddress((void**)&p_aql, g_aql);
    cudaGetSymbolAddress((void**)&p_ath, g_ath);  cudaGetSymbolAddress((void**)&p_atl, g_atl);
    cudaGetSymbolAddress((void**)&p_bvh, g_bvh);  cudaGetSymbolAddress((void**)&p_bvl, g_bvl);
    cudaGetSymbolAddress((void**)&p_bch, g_bch);  cudaGetSymbolAddress((void**)&p_bcl, g_bcl);
    cudaGetSymbolAddress((void**)&p_boh, g_boh);  cudaGetSymbolAddress((void**)&p_bol, g_bol);

    const int out_elems = NB * LQn * CC;        // 4194304
    const int locattn   = NB * LQn * MLP;       // 1048576
    bool full_out = (out_size >= out_elems + 2 * locattn);
    float* loc_out  = full_out ? (out + out_elems)           : p_loc2;
    float* attn_out = full_out ? (out + out_elems + locattn) : p_att2;

    const int smem_bytes = 8 * TILE_B;          // 81920
    cudaFuncSetAttribute(gemm_mma2_kernel,
                         cudaFuncAttributeMaxDynamicSharedMemorySize, smem_bytes);

    // ---- 1) weight prep + bias concat + activation hi/lo conv (one launch) --
    {
        int n40 = NB * SSt * KK / 4;            // 1966080
        int n41 = NB * LQn * KK / 4;            // 1048576
        int convBlks = (n40 + n41 + 255) / 256;
        prepconv_kernel<<<PREP_BLKS + convBlks, 256>>>(
            W_val, W_off, W_attn, W_out, b_off, b_attn,
            p_bvh, p_bvl, p_bch, p_bcl, p_boh, p_bol, p_bcat,
            inp, p_aih, p_ail, n40, query, p_aqh, p_aql, n41);
    }
    // ---- 2) value GEMM (480 tiles) + logits GEMM (256 tiles), one launch ----
    {
        int split = (NB * SSt / 128) * 2;       // 480
        int total = split + (NB * LQn / 128) * 2;   // 736
        gemm_mma2_kernel<<<total, 256, smem_bytes>>>(
            p_aih, p_ail, p_bvh, p_bvl, b_val,  p_value,
            p_aqh, p_aql, p_bch, p_bcl, p_bcat, p_logits,
            split);
    }
    // ---- 3) fused postproc + sampling (outputs 2&3 + bf16 A for out-GEMM) ----
    {
        int totalThreads = NB * LQn * MH * 32;
        sample_fused_kernel<<<totalThreads / 256, 256>>>(
            refpts, p_logits, loc_out, attn_out, p_ath, p_atl);
    }
    // ---- 4) out = sampled @ W_out + b_out (output 1) ----
    {
        int total = (NB * LQn / 128) * 2;       // 256
        gemm_mma2_kernel<<<total, 256, smem_bytes>>>(
            p_ath, p_atl, p_boh, p_bol, b_out, out,
            p_ath, p_atl, p_boh, p_bol, b_out, out,
            total);
    }
}

// round 15
// speedup vs baseline: 2.0035x; 1.0276x over previous
#include <cuda_runtime.h>
#include <cuda_bf16.h>
#include <cstdint>
#include <cstddef>

// Problem constants (static per reference)
#define NB  8
#define LQn 2048
#define CC  256
#define MH  8
#define LLv 4
#define DHd 32
#define SSt 3840
#define MLP 128   // M*L*P
#define KK  256   // GEMM K (= C)
#define NC  256   // GEMM N (all GEMMs are Nc=256 after fusion)

#define ASTR 40        // smem row stride in bf16 elems (80 B; 16B-aligned, conflict-free)
#define TILE_B (128 * ASTR * 2)   // 10240 B per 128x32 bf16 tile

// ---------------- scratch (__device__ globals; allocation-free rule) -------
__device__ float g_value [(size_t)NB * SSt * CC];   // value (N,S,M,DH) fp32
__device__ float g_logits[(size_t)NB * LQn * 256];  // [off(128) | attn(128)]
__device__ float g_loc2  [(size_t)NB * LQn * MLP];  // fallback outputs
__device__ float g_att2  [(size_t)NB * LQn * MLP];
__device__ float g_bcat  [256];

// bf16 hi/lo split activations (A matrices, row-major [R][256])
__device__ __nv_bfloat16 g_aih[(size_t)NB * SSt * KK];
__device__ __nv_bfloat16 g_ail[(size_t)NB * SSt * KK];
__device__ __nv_bfloat16 g_aqh[(size_t)NB * LQn * KK];
__device__ __nv_bfloat16 g_aql[(size_t)NB * LQn * KK];
__device__ __nv_bfloat16 g_ath[(size_t)NB * LQn * KK];
__device__ __nv_bfloat16 g_atl[(size_t)NB * LQn * KK];
// bf16 hi/lo transposed weights (B matrices, [Nc][256] K-major)
__device__ __nv_bfloat16 g_bvh[256 * KK], g_bvl[256 * KK];  // W_val^T
__device__ __nv_bfloat16 g_bch[256 * KK], g_bcl[256 * KK];  // [W_off|W_attn]^T
__device__ __nv_bfloat16 g_boh[256 * KK], g_bol[256 * KK];  // W_out^T

__device__ __forceinline__ uint32_t smem_u32(const void* p) {
    uint32_t a;
    asm("{ .reg .u64 t; cvta.to.shared.u64 t, %1; cvt.u32.u64 %0, t; }"
        : "=r"(a) : "l"(p));
    return a;
}

// ---------------------------------------------------------------------------
// mma.sync GEMM, dual-matrix dispatch: blocks [0,split) do matrix set 0,
// blocks [split, grid) do set 1. C[.,256] = (Ah+Al)(Bh+Bl)^T + bias,
// 3-term bf16 split, fp32 accumulate. CTA tile 128x128, 8 warps, BK=32,
// 3-stage cp.async pipeline (prefetch depth 2).
// ---------------------------------------------------------------------------
__global__ __launch_bounds__(256, 1)
void gemm_mma2_kernel(
    const __nv_bfloat16* __restrict__ Ah0, const __nv_bfloat16* __restrict__ Al0,
    const __nv_bfloat16* __restrict__ Bh0, const __nv_bfloat16* __restrict__ Bl0,
    const float* __restrict__ bias0, float* __restrict__ C0,
    const __nv_bfloat16* __restrict__ Ah1, const __nv_bfloat16* __restrict__ Al1,
    const __nv_bfloat16* __restrict__ Bh1, const __nv_bfloat16* __restrict__ Bl1,
    const float* __restrict__ bias1, float* __restrict__ C1,
    int split)
{
    extern __shared__ __align__(128) char smem[];
    uint32_t sb = smem_u32(smem);
    int tid  = threadIdx.x;
    int lane = tid & 31;
    int wid  = tid >> 5;
    int wr   = wid >> 2;     // 0..1  (m warp row)
    int wc   = wid & 3;      // 0..3  (n warp col)

    int bid = blockIdx.x;
    const __nv_bfloat16 *Ah, *Al, *Bh, *Bl;
    const float* bias;
    float* Cmat;
    int local;
    if (bid < split) {
        Ah = Ah0; Al = Al0; Bh = Bh0; Bl = Bl0; bias = bias0; Cmat = C0;
        local = bid;
    } else {
        Ah = Ah1; Al = Al1; Bh = Bh1; Bl = Bl1; bias = bias1; Cmat = C1;
        local = bid - split;
    }
    int bm = (local >> 1) * 128;
    int bn = (local & 1) * 128;

    const __nv_bfloat16* gtab[4] = {Ah + (size_t)bm * KK, Al + (size_t)bm * KK,
                                    Bh + (size_t)bn * KK, Bl + (size_t)bn * KK};
    int srow  = tid >> 1;          // 0..127
    int sboff = (tid & 1) * 32;    // 0 or 32 bytes within 64B row chunk

    float acc[4][4][4];
    #pragma unroll
    for (int i = 0; i < 4; i++)
        #pragma unroll
        for (int j = 0; j < 4; j++)
            #pragma unroll
            for (int r = 0; r < 4; r++) acc[i][j][r] = 0.f;

    int a_r = lane & 15;
    int a_k = (lane >> 4) << 3;
    int b_r = lane & 7;
    int b_k = ((lane >> 3) & 1) << 3;

    #define STAGE_LOAD(s, k0) do {                                              \
        _Pragma("unroll")                                                       \
        for (int t = 0; t < 4; t++) {                                           \
            uint32_t sdst = sb + (uint32_t)((s) * 4 + t) * TILE_B               \
                          + (uint32_t)srow * (ASTR * 2) + sboff;                \
            const char* gsrc = (const char*)(gtab[t] + (size_t)srow * KK + (k0))\
                             + sboff;                                           \
            asm volatile("cp.async.cg.shared.global [%0], [%1], 16;"            \
                         :: "r"(sdst), "l"(gsrc));                              \
            asm volatile("cp.async.cg.shared.global [%0], [%1], 16;"            \
                         :: "r"(sdst + 16), "l"(gsrc + 16));                    \
        }                                                                       \
        asm volatile("cp.async.commit_group;" ::: "memory");                    \
    } while (0)

    // 3-stage prologue: prefetch kt=0, kt=1
    STAGE_LOAD(0, 0);
    STAGE_LOAD(1, 32);

    int snext = 2;   // stage index to fill next
    for (int kt = 0; kt < 8; kt++) {
        if (kt < 6) {
            STAGE_LOAD(snext, (kt + 2) * 32);
            snext = (snext == 2) ? 0 : snext + 1;
            asm volatile("cp.async.wait_group 2;" ::: "memory");
        } else if (kt == 6) {
            asm volatile("cp.async.wait_group 1;" ::: "memory");
        } else {
            asm volatile("cp.async.wait_group 0;" ::: "memory");
        }
        __syncthreads();

        int s = kt % 3;
        uint32_t sAh = sb + (uint32_t)(s * 4 + 0) * TILE_B;
        uint32_t sAl = sb + (uint32_t)(s * 4 + 1) * TILE_B;
        uint32_t sBh = sb + (uint32_t)(s * 4 + 2) * TILE_B;
        uint32_t sBl = sb + (uint32_t)(s * 4 + 3) * TILE_B;

        #pragma unroll
        for (int kk = 0; kk < 32; kk += 16) {
            uint32_t ah[4][4], al[4][4], bh[4][2], bl[4][2];
            #pragma unroll
            for (int mi = 0; mi < 4; mi++) {
                int row = wr * 64 + mi * 16 + a_r;
                uint32_t off = (uint32_t)(row * ASTR + kk + a_k) * 2;
                asm volatile(
                    "ldmatrix.sync.aligned.m8n8.x4.shared.b16 {%0,%1,%2,%3}, [%4];"
                    : "=r"(ah[mi][0]), "=r"(ah[mi][1]), "=r"(ah[mi][2]), "=r"(ah[mi][3])
                    : "r"(sAh + off));
                asm volatile(
                    "ldmatrix.sync.aligned.m8n8.x4.shared.b16 {%0,%1,%2,%3}, [%4];"
                    : "=r"(al[mi][0]), "=r"(al[mi][1]), "=r"(al[mi][2]), "=r"(al[mi][3])
                    : "r"(sAl + off));
            }
            #pragma unroll
            for (int ni = 0; ni < 4; ni++) {
                int row = wc * 32 + ni * 8 + b_r;
                uint32_t off = (uint32_t)(row * ASTR + kk + b_k) * 2;
                asm volatile(
                    "ldmatrix.sync.aligned.m8n8.x2.shared.b16 {%0,%1}, [%2];"
                    : "=r"(bh[ni][0]), "=r"(bh[ni][1]) : "r"(sBh + off));
                asm volatile(
                    "ldmatrix.sync.aligned.m8n8.x2.shared.b16 {%0,%1}, [%2];"
                    : "=r"(bl[ni][0]), "=r"(bl[ni][1]) : "r"(sBl + off));
            }

            #define MMA(ACC, A, B)                                              \
                asm volatile(                                                   \
                    "mma.sync.aligned.m16n8k16.row.col.f32.bf16.bf16.f32 "      \
                    "{%0,%1,%2,%3}, {%4,%5,%6,%7}, {%8,%9}, {%0,%1,%2,%3};"     \
                    : "+f"((ACC)[0]), "+f"((ACC)[1]), "+f"((ACC)[2]), "+f"((ACC)[3]) \
                    : "r"((A)[0]), "r"((A)[1]), "r"((A)[2]), "r"((A)[3]),       \
                      "r"((B)[0]), "r"((B)[1]))

            #pragma unroll
            for (int mi = 0; mi < 4; mi++)
                #pragma unroll
                for (int ni = 0; ni < 4; ni++) {
                    MMA(acc[mi][ni], ah[mi], bh[ni]);   // Ah*Bh
                    MMA(acc[mi][ni], al[mi], bh[ni]);   // Al*Bh
                    MMA(acc[mi][ni], ah[mi], bl[ni]);   // Ah*Bl
                }
            #undef MMA
        }
        __syncthreads();
    }
    #undef STAGE_LOAD

    // ---- epilogue: fp32 + bias ----
    int r0 = bm + wr * 64;
    int c0 = bn + wc * 32;
    #pragma unroll
    for (int mi = 0; mi < 4; mi++) {
        int row = r0 + mi * 16 + (lane >> 2);
        #pragma unroll
        for (int ni = 0; ni < 4; ni++) {
            int col = c0 + ni * 8 + (lane & 3) * 2;
            float2 bv = *(const float2*)(bias + col);
            float2 v0 = {acc[mi][ni][0] + bv.x, acc[mi][ni][1] + bv.y};
            float2 v1 = {acc[mi][ni][2] + bv.x, acc[mi][ni][3] + bv.y};
            *(float2*)(Cmat + (size_t)row * NC + col)       = v0;
            *(float2*)(Cmat + (size_t)(row + 8) * NC + col) = v1;
        }
    }
}

// ---------------------------------------------------------------------------
// Combined prep + activation conversion (one launch).
// ---------------------------------------------------------------------------
#define PREP_ITEMS (3 * 65536 + 256)
#define PREP_BLKS  ((PREP_ITEMS + 255) / 256)

__global__ __launch_bounds__(256) void prepconv_kernel(
    const float* __restrict__ W_val, const float* __restrict__ W_off,
    const float* __restrict__ W_attn, const float* __restrict__ W_out,
    const float* __restrict__ b_off, const float* __restrict__ b_attn,
    __nv_bfloat16* __restrict__ bvh, __nv_bfloat16* __restrict__ bvl,
    __nv_bfloat16* __restrict__ bch, __nv_bfloat16* __restrict__ bcl,
    __nv_bfloat16* __restrict__ boh, __nv_bfloat16* __restrict__ bol,
    float* __restrict__ bcat,
    const float* __restrict__ s0, __nv_bfloat16* __restrict__ h0,
    __nv_bfloat16* __restrict__ l0, int n40,
    const float* __restrict__ s1, __nv_bfloat16* __restrict__ h1,
    __nv_bfloat16* __restrict__ l1, int n41)
{
    if (blockIdx.x < PREP_BLKS) {
        int gid = blockIdx.x * 256 + threadIdx.x;
        if (gid >= 3 * 65536) {
            int i = gid - 3 * 65536;
            if (i < 256) bcat[i] = (i < 128) ? b_off[i] : b_attn[i - 128];
            return;
        }
        int which = gid >> 16;
        int idx   = gid & 65535;
        int n = idx >> 8, k = idx & 255;
        float v;
        __nv_bfloat16 *dh, *dl;
        if (which == 0) {
            v = W_val[(size_t)k * 256 + n]; dh = bvh; dl = bvl;
        } else if (which == 1) {
            v = (n < 128) ? W_off[(size_t)k * 128 + n]
                          : W_attn[(size_t)k * 128 + (n - 128)];
            dh = bch; dl = bcl;
        } else {
            v = W_out[(size_t)k * 256 + n]; dh = boh; dl = bol;
        }
        __nv_bfloat16 h = __float2bfloat16(v);
        dh[idx] = h;
        dl[idx] = __float2bfloat16(v - __bfloat162float(h));
        return;
    }

    int i = (blockIdx.x - PREP_BLKS) * 256 + threadIdx.x;
    const float* s; __nv_bfloat16 *H8, *L8; int j;
    if (i < n40) { s = s0; H8 = h0; L8 = l0; j = i; }
    else {
        j = i - n40;
        if (j >= n41) return;
        s = s1; H8 = h1; L8 = l1;
    }
    float4 v = ((const float4*)s)[j];
    __nv_bfloat16 a0 = __float2bfloat16(v.x), a1 = __float2bfloat16(v.y);
    __nv_bfloat16 a2 = __float2bfloat16(v.z), a3 = __float2bfloat16(v.w);
    __nv_bfloat16 c0 = __float2bfloat16(v.x - __bfloat162float(a0));
    __nv_bfloat16 c1 = __float2bfloat16(v.y - __bfloat162float(a1));
    __nv_bfloat16 c2 = __float2bfloat16(v.z - __bfloat162float(a2));
    __nv_bfloat16 c3 = __float2bfloat16(v.w - __bfloat162float(a3));
    __nv_bfloat162* H = (__nv_bfloat162*)H8;
    __nv_bfloat162* L = (__nv_bfloat162*)L8;
    H[2 * j]     = __nv_bfloat162(a0, a1);
    H[2 * j + 1] = __nv_bfloat162(a2, a3);
    L[2 * j]     = __nv_bfloat162(c0, c1);
    L[2 * j + 1] = __nv_bfloat162(c2, c3);
}

// ---------------------------------------------------------------------------
// Fused postproc + sampling. Warp per (n,q,m).
// Setup: lanes 0-15 own one (l,p) slot (softmax, loc, bilinear weights/rows).
// Gather: lane=(grp,c): 8 lanes x float4 cover the 32 channels of one point;
// 4 points in flight -> 4 iterations of {3 shfl, 2 LDG.128, 8 FFMA}.
// Butterfly-reduce over groups, lanes 0-7 write bf16 hi/lo.
// ---------------------------------------------------------------------------
__global__ __launch_bounds__(256) void sample_fused_kernel(
    const float* __restrict__ refpts, const float* __restrict__ logits,
    float* __restrict__ loc_out, float* __restrict__ attn_out,
    __nv_bfloat16* __restrict__ outh, __nv_bfloat16* __restrict__ outl)
{
    int gwarp = blockIdx.x * 8 + (threadIdx.x >> 5);   // (n,q,m), < 131072
    int lane  = threadIdx.x & 31;
    int m  = gwarp & 7;
    int nq = gwarp >> 3;
    int n  = nq >> 11;                 // / LQn

    // --- softmax + loc on 16 slots (owner lanes 0-15; 16-31 mirror) ---
    int li = lane & 15;
    const float* lrow = logits + nq * 256 + m * 16;
    float offv = lrow[li];
    float lgv  = lrow[128 + li];
    float mx = lgv;
    #pragma unroll
    for (int d = 1; d < 16; d <<= 1)
        mx = fmaxf(mx, __shfl_xor_sync(0xffffffffu, mx, d));
    float ev = __expf(lgv - mx);
    float sum = ev;
    #pragma unroll
    for (int d = 1; d < 16; d <<= 1)
        sum += __shfl_xor_sync(0xffffffffu, sum, d);
    float attnv = ev / sum;

    const float innorm[4] = {1.f / 2048.f, 1.f / 1024.f, 1.f / 512.f, 1.f / 256.f};
    int lv = li >> 2;
    float rn = refpts[nq * 4 + lv];
    float locv = rn + offv * innorm[lv];

    if (lane < 16) {
        loc_out [gwarp * 16 + lane] = locv;
        attn_out[gwarp * 16 + lane] = attnv;
    }

    // --- per-slot bilinear setup (owner lanes; mirrored in 16-31) ---
    const int lens[4]   = {2048, 1024, 512, 256};
    const int starts[4] = {0, 2048, 3072, 3584};
    int T = lens[lv], st = starts[lv];
    float pos = locv * (float)T - 0.5f;
    float x0f = floorf(pos);
    float frac = pos - x0f;
    int x0 = (int)x0f;
    float w0 = (x0 >= 0 && x0 < T)         ? (1.f - frac) : 0.f;
    float w1 = (x0 + 1 >= 0 && x0 + 1 < T) ? frac         : 0.f;
    float aw0 = attnv * w0;
    float aw1 = attnv * w1;
    int i0 = min(max(x0, 0), T - 1) + st;       // absolute row in [0, 3840)
    int i1 = min(max(x0 + 1, 0), T - 1) + st;
    int packed = i0 | (i1 << 16);

    // --- gather: float4-wide, 4 points concurrently ---
    int grp = lane >> 3;                // 0..3 (point group)
    int c4  = (lane & 7) << 2;          // channel base 0,4,...,28
    const float* vbase = g_value + (n * SSt * CC + m * DHd + c4);
    float4 acc4 = {0.f, 0.f, 0.f, 0.f};
    #pragma unroll
    for (int t = 0; t < 4; t++) {
        int src = t * 4 + grp;          // point index 0..15
        float a0 = __shfl_sync(0xffffffffu, aw0, src);
        float a1 = __shfl_sync(0xffffffffu, aw1, src);
        int   pk = __shfl_sync(0xffffffffu, packed, src);
        int o0 = (pk & 0xFFFF) << 8;    // row * 256 floats
        int o1 = ((unsigned)pk >> 16) << 8;
        float4 v0 = *(const float4*)(vbase + o0);
        float4 v1 = *(const float4*)(vbase + o1);
        acc4.x += a0 * v0.x + a1 * v1.x;
        acc4.y += a0 * v0.y + a1 * v1.y;
        acc4.z += a0 * v0.z + a1 * v1.z;
        acc4.w += a0 * v0.w + a1 * v1.w;
    }
    // reduce across the 4 point groups (lanes differing in bits 3,4)
    #pragma unroll
    for (int d = 8; d <= 16; d <<= 1) {
        acc4.x += __shfl_xor_sync(0xffffffffu, acc4.x, d);
        acc4.y += __shfl_xor_sync(0xffffffffu, acc4.y, d);
        acc4.z += __shfl_xor_sync(0xffffffffu, acc4.z, d);
        acc4.w += __shfl_xor_sync(0xffffffffu, acc4.w, d);
    }

    if (lane < 8) {
        __nv_bfloat16 hx = __float2bfloat16(acc4.x);
        __nv_bfloat16 hy = __float2bfloat16(acc4.y);
        __nv_bfloat16 hz = __float2bfloat16(acc4.z);
        __nv_bfloat16 hw = __float2bfloat16(acc4.w);
        __nv_bfloat162* H2 = (__nv_bfloat162*)(outh + (size_t)gwarp * DHd + c4);
        H2[0] = __nv_bfloat162(hx, hy);
        H2[1] = __nv_bfloat162(hz, hw);
        __nv_bfloat16 lx = __float2bfloat16(acc4.x - __bfloat162float(hx));
        __nv_bfloat16 ly = __float2bfloat16(acc4.y - __bfloat162float(hy));
        __nv_bfloat16 lz = __float2bfloat16(acc4.z - __bfloat162float(hz));
        __nv_bfloat16 lw = __float2bfloat16(acc4.w - __bfloat162float(hw));
        __nv_bfloat162* L2p = (__nv_bfloat162*)(outl + (size_t)gwarp * DHd + c4);
        L2p[0] = __nv_bfloat162(lx, ly);
        L2p[1] = __nv_bfloat162(lz, lw);
    }
}

// ---------------------------------------------------------------------------
extern "C" void kernel_launch(void* const* d_in, const int* in_sizes, int n_in,
                              void* d_out, int out_size)
{
    const float* query  = (const float*)d_in[0];
    const float* refpts = (const float*)d_in[1];
    const float* inp    = (const float*)d_in[2];
    const float* W_off  = (const float*)d_in[5];
    const float* b_off  = (const float*)d_in[6];
    const float* W_attn = (const float*)d_in[7];
    const float* b_attn = (const float*)d_in[8];
    const float* W_val  = (const float*)d_in[9];
    const float* b_val  = (const float*)d_in[10];
    const float* W_out  = (const float*)d_in[11];
    const float* b_out  = (const float*)d_in[12];
    float* out = (float*)d_out;

    float *p_value, *p_logits, *p_loc2, *p_att2, *p_bcat;
    __nv_bfloat16 *p_aih, *p_ail, *p_aqh, *p_aql, *p_ath, *p_atl;
    __nv_bfloat16 *p_bvh, *p_bvl, *p_bch, *p_bcl, *p_boh, *p_bol;
    cudaGetSymbolAddress((void**)&p_value,  g_value);
    cudaGetSymbolAddress((void**)&p_logits, g_logits);
    cudaGetSymbolAddress((void**)&p_loc2,   g_loc2);
    cudaGetSymbolAddress((void**)&p_att2,   g_att2);
    cudaGetSymbolAddress((void**)&p_bcat,   g_bcat);
    cudaGetSymbolAddress((void**)&p_aih, g_aih);  cudaGetSymbolAddress((void**)&p_ail, g_ail);
    cudaGetSymbolAddress((void**)&p_aqh, g_aqh);  cudaGetSymbolAddress((void**)&p_aql, g_aql);
    cudaGetSymbolAddress((void**)&p_ath, g_ath);  cudaGetSymbolAddress((void**)&p_atl, g_atl);
    cudaGetSymbolAddress((void**)&p_bvh, g_bvh);  cudaGetSymbolAddress((void**)&p_bvl, g_bvl);
    cudaGetSymbolAddress((void**)&p_bch, g_bch);  cudaGetSymbolAddress((void**)&p_bcl, g_bcl);
    cudaGetSymbolAddress((void**)&p_boh, g_boh);  cudaGetSymbolAddress((void**)&p_bol, g_bol);

    const int out_elems = NB * LQn * CC;        // 4194304
    const int locattn   = NB * LQn * MLP;       // 1048576
    bool full_out = (out_size >= out_elems + 2 * locattn);
    float* loc_out  = full_out ? (out + out_elems)           : p_loc2;
    float* attn_out = full_out ? (out + out_elems + locattn) : p_att2;

    const int smem_bytes = 12 * TILE_B;         // 122880 (3-stage)
    cudaFuncSetAttribute(gemm_mma2_kernel,
                         cudaFuncAttributeMaxDynamicSharedMemorySize, smem_bytes);

    // ---- 1) weight prep + bias concat + activation hi/lo conv (one launch) --
    {
        int n40 = NB * SSt * KK / 4;            // 1966080
        int n41 = NB * LQn * KK / 4;            // 1048576
        int convBlks = (n40 + n41 + 255) / 256;
        prepconv_kernel<<<PREP_BLKS + convBlks, 256>>>(
            W_val, W_off, W_attn, W_out, b_off, b_attn,
            p_bvh, p_bvl, p_bch, p_bcl, p_boh, p_bol, p_bcat,
            inp, p_aih, p_ail, n40, query, p_aqh, p_aql, n41);
    }
    // ---- 2) value GEMM (480 tiles) + logits GEMM (256 tiles), one launch ----
    {
        int split = (NB * SSt / 128) * 2;       // 480
        int total = split + (NB * LQn / 128) * 2;   // 736
        gemm_mma2_kernel<<<total, 256, smem_bytes>>>(
            p_aih, p_ail, p_bvh, p_bvl, b_val,  p_value,
            p_aqh, p_aql, p_bch, p_bcl, p_bcat, p_logits,
            split);
    }
    // ---- 3) fused postproc + sampling (outputs 2&3 + bf16 A for out-GEMM) ----
    {
        int totalThreads = NB * LQn * MH * 32;
        sample_fused_kernel<<<totalThreads / 256, 256>>>(
            refpts, p_logits, loc_out, attn_out, p_ath, p_atl);
    }
    // ---- 4) out = sampled @ W_out + b_out (output 1) ----
    {
        int total = (NB * LQn / 128) * 2;       // 256
        gemm_mma2_kernel<<<total, 256, smem_bytes>>>(
            p_ath, p_atl, p_boh, p_bol, b_out, out,
            p_ath, p_atl, p_boh, p_bol, b_out, out,
            total);
    }
}